// round 5
// baseline (speedup 1.0000x reference)
#include <cuda_runtime.h>
#include <math.h>
#include <stdint.h>

// Problem dims (fixed)
#define Bdim 2
#define Mdim 2048
#define Ndim 2048
#define Edim 128
#define Kdim 8
#define Ddim 16
#define NHEAD (Bdim * Kdim)

// Static scratch.
// g_Q : plain [head][n][d] fp32
// g_K : tf32 HI, mma B-fragment packed: [head][kb][lane][4]
//       lane = 4*(key&7)+j (j=d&3), component = d>>2
// g_K2: tf32 LO residual, same layout
// g_V : tf32-truncated, B-fragment packed for PV:
//       lane = 16*((d>>2)&1) + 4*(d&3) + (key&3), comp = ((key>>2)&1) | ((d>>3)<<1)
// g_O : [b][n][k][d]
__device__ float g_Q [NHEAD * (size_t)Ndim * Ddim];
__device__ float g_K [NHEAD * (size_t)Mdim * Ddim];
__device__ float g_K2[NHEAD * (size_t)Mdim * Ddim];
__device__ float g_V [NHEAD * (size_t)Mdim * Ddim];
__device__ float g_O [Bdim * (size_t)Ndim * Kdim * Ddim];

__device__ __forceinline__ float ex2f(float x) {
    float r; asm("ex2.approx.f32 %0, %1;" : "=f"(r) : "f"(x)); return r;
}
__device__ __forceinline__ uint32_t to_tf32(float f) {
    uint32_t r; asm("cvt.rna.tf32.f32 %0, %1;" : "=r"(r) : "f"(f)); return r;
}
// D += A(tf32 m16k8) * B(tf32 k8n8)
__device__ __forceinline__ void mma_tf32(float& d0, float& d1, float& d2, float& d3,
                                         uint32_t a0, uint32_t a1, uint32_t a2, uint32_t a3,
                                         uint32_t b0, uint32_t b1) {
    asm volatile("mma.sync.aligned.m16n8k8.row.col.f32.tf32.tf32.f32 "
                 "{%0,%1,%2,%3},{%4,%5,%6,%7},{%8,%9},{%0,%1,%2,%3};"
                 : "+f"(d0), "+f"(d1), "+f"(d2), "+f"(d3)
                 : "r"(a0), "r"(a1), "r"(a2), "r"(a3), "r"(b0), "r"(b1));
}
// D = A*B (zero C) — starts a fresh accumulation chain
__device__ __forceinline__ void mma_tf32_z(float& d0, float& d1, float& d2, float& d3,
                                           uint32_t a0, uint32_t a1, uint32_t a2, uint32_t a3,
                                           uint32_t b0, uint32_t b1) {
    asm volatile("mma.sync.aligned.m16n8k8.row.col.f32.tf32.tf32.f32 "
                 "{%0,%1,%2,%3},{%4,%5,%6,%7},{%8,%9},{%10,%10,%10,%10};"
                 : "=f"(d0), "=f"(d1), "=f"(d2), "=f"(d3)
                 : "r"(a0), "r"(a1), "r"(a2), "r"(a3), "r"(b0), "r"(b1), "f"(0.f));
}

// ---------------------------------------------------------------------------
// Kernel 1: fused projections. 256 thr, 8 warps, 2 rows/warp = 16 rows/block.
// Writes Q plain; K hi/lo tf32-split and V tf32-truncated, fragment-packed.
// ---------------------------------------------------------------------------
__global__ __launch_bounds__(256) void proj_kernel(
    const float* __restrict__ x, const float* __restrict__ y,
    const float* __restrict__ l1, const float* __restrict__ l2,
    const float* __restrict__ t1, const float* __restrict__ bl)
{
    __shared__ float xs[16][Edim];
    __shared__ float ys[16][Edim];
    const int tid  = threadIdx.x;
    const int w    = tid >> 5;
    const int lane = tid & 31;
    const int row0 = blockIdx.x * 16;

    {
        const float4* xg = reinterpret_cast<const float4*>(x + (size_t)row0 * Edim);
        const float4* yg = reinterpret_cast<const float4*>(y + (size_t)row0 * Edim);
        float4* xs4 = reinterpret_cast<float4*>(&xs[0][0]);
        float4* ys4 = reinterpret_cast<float4*>(&ys[0][0]);
        #pragma unroll
        for (int i = 0; i < 2; i++) {
            xs4[tid + i * 256] = xg[tid + i * 256];
            ys4[tid + i * 256] = yg[tid + i * 256];
        }
    }
    __syncthreads();

    const int k  = lane >> 2;      // head-in-batch 0..7
    const int dq = lane & 3;       // d-quad

    const float4* l1v = reinterpret_cast<const float4*>(l1);
    const float4* l2v = reinterpret_cast<const float4*>(l2);
    const float4* t1v = reinterpret_cast<const float4*>(t1);

    float4 ka[2], va[2], qa[2];
    #pragma unroll
    for (int r = 0; r < 2; r++) {
        ka[r] = make_float4(0.f,0.f,0.f,0.f);
        va[r] = make_float4(0.f,0.f,0.f,0.f);
        qa[r] = make_float4(0.f,0.f,0.f,0.f);
    }

    #pragma unroll 4
    for (int e = 0; e < Edim; e++) {
        const int wi = (k * Edim + e) * 4 + dq;
        const float4 A  = l1v[wi];
        const float4 C  = t1v[wi];
        const float4 Qw = l2v[wi];
        #pragma unroll
        for (int r = 0; r < 2; r++) {
            const float xv = xs[w * 2 + r][e];
            const float yv = ys[w * 2 + r][e];
            ka[r].x += xv * A.x;  ka[r].y += xv * A.y;  ka[r].z += xv * A.z;  ka[r].w += xv * A.w;
            va[r].x += xv * C.x;  va[r].y += xv * C.y;  va[r].z += xv * C.z;  va[r].w += xv * C.w;
            qa[r].x += yv * Qw.x; qa[r].y += yv * Qw.y; qa[r].z += yv * Qw.z; qa[r].w += yv * Qw.w;
        }
    }

    const float4 bb = reinterpret_cast<const float4*>(bl)[k * 4 + dq];
    #pragma unroll
    for (int r = 0; r < 2; r++) {
        ka[r].x += bb.x; ka[r].y += bb.y; ka[r].z += bb.z; ka[r].w += bb.w;
        const int row = row0 + w * 2 + r;
        const int b   = row / Mdim;
        const int m   = row % Mdim;
        const int head = b * Kdim + k;

        // Q: plain [head][m][d], float4
        reinterpret_cast<float4*>(g_Q)[(((size_t)head * Mdim + m) * Ddim) / 4 + dq] = qa[r];

        // K: tf32 hi/lo split, fragment-packed.
        {
            const size_t kpb = ((size_t)head * (Mdim / 8) + (m >> 3)) * 128;
            const float kv[4] = {ka[r].x, ka[r].y, ka[r].z, ka[r].w};
            #pragma unroll
            for (int j = 0; j < 4; j++) {
                const float hi = __uint_as_float(to_tf32(kv[j]));
                const float lo = __uint_as_float(to_tf32(kv[j] - hi));
                const size_t off = kpb + (size_t)(4 * (m & 7) + j) * 4 + dq;
                g_K [off] = hi;
                g_K2[off] = lo;
            }
        }
        // V: tf32-truncated, fragment-packed.
        {
            const size_t vpb = ((size_t)head * (Mdim / 8) + (m >> 3)) * 128;
            const int c = ((m >> 2) & 1) | ((dq >> 1) << 1);
            const float vv[4] = {va[r].x, va[r].y, va[r].z, va[r].w};
            #pragma unroll
            for (int j = 0; j < 4; j++)
                g_V[vpb + (size_t)(16 * (dq & 1) + 4 * j + (m & 3)) * 4 + c] =
                    __uint_as_float(to_tf32(vv[j]));
        }
    }
}

// ---------------------------------------------------------------------------
// Kernel 2: flash attention via 3xTF32 mma.m16n8k8. No smem, no max-tracking
// (logits bounded in fp32 range; softmax shift-invariance makes this exact).
// Warp = 32 queries (2 A-fragments) x all 2048 keys; block = 4 warps = 128 q.
// Grid = (2048/128, 16 heads) = 256 blocks.
// ---------------------------------------------------------------------------
__global__ __launch_bounds__(128) void flash_kernel(const float* __restrict__ bt)
{
    const int head = blockIdx.y;
    const int warp = threadIdx.x >> 5;
    const int lane = threadIdx.x & 31;
    const int g = lane >> 2, t = lane & 3;
    const int qb = blockIdx.x * 128 + warp * 32;

    const float sc = 0.25f * 1.4426950408889634f;   // d^-1/2 * log2(e)

    // Q A-fragments, hi/lo tf32 split. frag f covers rows qb+16f .. qb+16f+15.
    const float* Qh = g_Q + ((size_t)head * Ndim + qb) * Ddim;
    uint32_t qhi[2][8], qlo[2][8];
    #pragma unroll
    for (int f = 0; f < 2; f++) {
        #pragma unroll
        for (int c = 0; c < 2; c++) {
            const float v0 = Qh[(16*f + g    ) * Ddim + t     + 8*c] * sc;
            const float v1 = Qh[(16*f + g + 8) * Ddim + t     + 8*c] * sc;
            const float v2 = Qh[(16*f + g    ) * Ddim + t + 4 + 8*c] * sc;
            const float v3 = Qh[(16*f + g + 8) * Ddim + t + 4 + 8*c] * sc;
            qhi[f][4*c+0] = to_tf32(v0); qlo[f][4*c+0] = to_tf32(v0 - __uint_as_float(qhi[f][4*c+0]));
            qhi[f][4*c+1] = to_tf32(v1); qlo[f][4*c+1] = to_tf32(v1 - __uint_as_float(qhi[f][4*c+1]));
            qhi[f][4*c+2] = to_tf32(v2); qlo[f][4*c+2] = to_tf32(v2 - __uint_as_float(qhi[f][4*c+2]));
            qhi[f][4*c+3] = to_tf32(v3); qlo[f][4*c+3] = to_tf32(v3 - __uint_as_float(qhi[f][4*c+3]));
        }
    }

    float o[2][8];
    float lsum[2][2];
    #pragma unroll
    for (int f = 0; f < 2; f++) {
        #pragma unroll
        for (int i = 0; i < 8; i++) o[f][i] = 0.f;
        lsum[f][0] = 0.f; lsum[f][1] = 0.f;
    }

    const float4* Kp  = reinterpret_cast<const float4*>(g_K ) + (size_t)head * (Mdim / 8) * 32;
    const float4* K2p = reinterpret_cast<const float4*>(g_K2) + (size_t)head * (Mdim / 8) * 32;
    const float4* Vp  = reinterpret_cast<const float4*>(g_V ) + (size_t)head * (Mdim / 8) * 32;

    const int src  = (lane & ~3) | (t >> 1);
    const int src2 = src + 2;
    const bool odd = (t & 1);

    float4 kh = Kp[lane];
    float4 kl = K2p[lane];
    float4 vf = Vp[lane];

    #pragma unroll 2
    for (int kb = 0; kb < Mdim / 8; kb++) {
        float4 kh_n, kl_n, vf_n;
        if (kb + 1 < Mdim / 8) {
            kh_n = Kp [(kb + 1) * 32 + lane];
            kl_n = K2p[(kb + 1) * 32 + lane];
            vf_n = Vp [(kb + 1) * 32 + lane];
        }
        const uint32_t bh0 = __float_as_uint(kh.x), bh1 = __float_as_uint(kh.y);
        const uint32_t bh2 = __float_as_uint(kh.z), bh3 = __float_as_uint(kh.w);
        const uint32_t bl0 = __float_as_uint(kl.x), bl1 = __float_as_uint(kl.y);
        const uint32_t bl2 = __float_as_uint(kl.z), bl3 = __float_as_uint(kl.w);
        const uint32_t bv0 = __float_as_uint(vf.x), bv1 = __float_as_uint(vf.y);
        const uint32_t bv2 = __float_as_uint(vf.z), bv3 = __float_as_uint(vf.w);

        #pragma unroll
        for (int f = 0; f < 2; f++) {
            // S = Q*K^T with 3xTF32 compensation; two independent chains (d-chunks)
            float sA0, sA1, sA2, sA3, sB0, sB1, sB2, sB3;
            mma_tf32_z(sA0, sA1, sA2, sA3, qhi[f][0], qhi[f][1], qhi[f][2], qhi[f][3], bh0, bh1);
            mma_tf32_z(sB0, sB1, sB2, sB3, qhi[f][4], qhi[f][5], qhi[f][6], qhi[f][7], bh2, bh3);
            mma_tf32(sA0, sA1, sA2, sA3, qlo[f][0], qlo[f][1], qlo[f][2], qlo[f][3], bh0, bh1);
            mma_tf32(sB0, sB1, sB2, sB3, qlo[f][4], qlo[f][5], qlo[f][6], qlo[f][7], bh2, bh3);
            mma_tf32(sA0, sA1, sA2, sA3, qhi[f][0], qhi[f][1], qhi[f][2], qhi[f][3], bl0, bl1);
            mma_tf32(sB0, sB1, sB2, sB3, qhi[f][4], qhi[f][5], qhi[f][6], qhi[f][7], bl2, bl3);

            // p = 2^s, truncated to tf32 so that l and P*V use identical weights
            const float p0 = __uint_as_float(to_tf32(ex2f(sA0 + sB0)));
            const float p1 = __uint_as_float(to_tf32(ex2f(sA1 + sB1)));
            const float p2 = __uint_as_float(to_tf32(ex2f(sA2 + sB2)));
            const float p3 = __uint_as_float(to_tf32(ex2f(sA3 + sB3)));
            lsum[f][0] += p0 + p1;
            lsum[f][1] += p2 + p3;

            // permute P from C-layout to A-layout
            const float x0 = __shfl_sync(0xffffffffu, p0, src);
            const float x1 = __shfl_sync(0xffffffffu, p1, src);
            const float x2 = __shfl_sync(0xffffffffu, p2, src);
            const float x3 = __shfl_sync(0xffffffffu, p3, src);
            const float y0 = __shfl_sync(0xffffffffu, p0, src2);
            const float y1 = __shfl_sync(0xffffffffu, p1, src2);
            const float y2 = __shfl_sync(0xffffffffu, p2, src2);
            const float y3 = __shfl_sync(0xffffffffu, p3, src2);
            const uint32_t a0 = __float_as_uint(odd ? x1 : x0);
            const uint32_t a1 = __float_as_uint(odd ? x3 : x2);
            const uint32_t a2 = __float_as_uint(odd ? y1 : y0);
            const uint32_t a3 = __float_as_uint(odd ? y3 : y2);

            mma_tf32(o[f][0], o[f][1], o[f][2], o[f][3], a0, a1, a2, a3, bv0, bv1);
            mma_tf32(o[f][4], o[f][5], o[f][6], o[f][7], a0, a1, a2, a3, bv2, bv3);
        }
        kh = kh_n; kl = kl_n; vf = vf_n;
    }

    const int b = head >> 3, k = head & 7;
    #pragma unroll
    for (int f = 0; f < 2; f++) {
        float l0 = lsum[f][0], l1 = lsum[f][1];
        l0 += __shfl_xor_sync(0xffffffffu, l0, 1);
        l0 += __shfl_xor_sync(0xffffffffu, l0, 2);
        l1 += __shfl_xor_sync(0xffffffffu, l1, 1);
        l1 += __shfl_xor_sync(0xffffffffu, l1, 2);
        const float inv0 = 1.f / l0;
        const float inv1 = 1.f / l1;
        const int rlo = qb + 16*f + g;
        const int rhi = rlo + 8;
        #pragma unroll
        for (int c = 0; c < 2; c++) {
            const int d0 = 8 * c + 2 * t;
            float2 r_lo, r_hi;
            r_lo.x = o[f][4*c+0] * inv0 + bt[k * Ddim + d0];
            r_lo.y = o[f][4*c+1] * inv0 + bt[k * Ddim + d0 + 1];
            r_hi.x = o[f][4*c+2] * inv1 + bt[k * Ddim + d0];
            r_hi.y = o[f][4*c+3] * inv1 + bt[k * Ddim + d0 + 1];
            float* lo = g_O + (((size_t)(b * Ndim + rlo) * Kdim) + k) * Ddim + d0;
            float* hi = g_O + (((size_t)(b * Ndim + rhi) * Kdim) + k) * Ddim + d0;
            *reinterpret_cast<float2*>(lo) = r_lo;
            *reinterpret_cast<float2*>(hi) = r_hi;
        }
    }
}

// ---------------------------------------------------------------------------
// Kernel 3: output projection, 4 rows/block (grid 1024 for occupancy).
// ---------------------------------------------------------------------------
__global__ __launch_bounds__(128) void out_kernel(const float* __restrict__ t2,
                                                  float* __restrict__ out)
{
    __shared__ __align__(16) float orow[4][Kdim * Ddim];
    const int row0 = blockIdx.x * 4;
    const int e = threadIdx.x;   // 0..127

    #pragma unroll
    for (int r = 0; r < 4; r++)
        orow[r][e] = g_O[(size_t)(row0 + r) * (Kdim * Ddim) + e];
    __syncthreads();

    float acc[4];
    #pragma unroll
    for (int r = 0; r < 4; r++) acc[r] = 0.f;

    const float4* t2v = reinterpret_cast<const float4*>(t2);
    #pragma unroll
    for (int k = 0; k < Kdim; k++) {
        const int base = (k * Edim + e) * 4;
        #pragma unroll
        for (int dq = 0; dq < 4; dq++) {
            const float4 wv = t2v[base + dq];
            #pragma unroll
            for (int r = 0; r < 4; r++) {
                const float4 oo = *reinterpret_cast<const float4*>(&orow[r][k * Ddim + dq * 4]);
                acc[r] += wv.x * oo.x + wv.y * oo.y + wv.z * oo.z + wv.w * oo.w;
            }
        }
    }
    #pragma unroll
    for (int r = 0; r < 4; r++)
        out[(size_t)(row0 + r) * Edim + e] = acc[r];
}

extern "C" void kernel_launch(void* const* d_in, const int* in_sizes, int n_in,
                              void* d_out, int out_size)
{
    const float* x  = (const float*)d_in[0];
    const float* y  = (const float*)d_in[1];
    const float* l1 = (const float*)d_in[2];
    const float* l2 = (const float*)d_in[3];
    const float* t1 = (const float*)d_in[4];
    const float* t2 = (const float*)d_in[5];
    const float* bl = (const float*)d_in[6];
    const float* bt = (const float*)d_in[7];

    proj_kernel<<<Bdim * Mdim / 16, 256>>>(x, y, l1, l2, t1, bl);
    flash_kernel<<<dim3(Ndim / 128, NHEAD), 128>>>(bt);
    out_kernel<<<Bdim * Ndim / 4, 128>>>(t2, (float*)d_out);
}

// round 6
// speedup vs baseline: 1.5300x; 1.5300x over previous
#include <cuda_runtime.h>
#include <math.h>
#include <stdint.h>

// Problem dims (fixed)
#define Bdim 2
#define Mdim 2048
#define Ndim 2048
#define Edim 128
#define Kdim 8
#define Ddim 16
#define NHEAD (Bdim * Kdim)
#define SPLIT 4
#define MCHUNK (Mdim / SPLIT)   // 512 keys per split

// Static scratch.
// g_Q : plain [head][n][d] fp32
// g_K : tf32 HI, mma B-fragment packed  [head][kb][lane][4]
// g_K2: tf32 LO residual, same layout
// g_V : tf32-truncated, B-fragment packed for PV
// g_O : [b][n][k][d]
// g_Po/g_Pl: split partials (no max needed — plain additive sums)
__device__ float g_Q [NHEAD * (size_t)Ndim * Ddim];
__device__ float g_K [NHEAD * (size_t)Mdim * Ddim];
__device__ float g_K2[NHEAD * (size_t)Mdim * Ddim];
__device__ float g_V [NHEAD * (size_t)Mdim * Ddim];
__device__ float g_O [Bdim * (size_t)Ndim * Kdim * Ddim];
__device__ float g_Po[NHEAD * (size_t)SPLIT * Ndim * Ddim];
__device__ float g_Pl[NHEAD * (size_t)SPLIT * Ndim];

__device__ __forceinline__ float ex2f(float x) {
    float r; asm("ex2.approx.f32 %0, %1;" : "=f"(r) : "f"(x)); return r;
}
__device__ __forceinline__ uint32_t to_tf32(float f) {
    uint32_t r; asm("cvt.rna.tf32.f32 %0, %1;" : "=r"(r) : "f"(f)); return r;
}
__device__ __forceinline__ void mma_tf32(float& d0, float& d1, float& d2, float& d3,
                                         uint32_t a0, uint32_t a1, uint32_t a2, uint32_t a3,
                                         uint32_t b0, uint32_t b1) {
    asm volatile("mma.sync.aligned.m16n8k8.row.col.f32.tf32.tf32.f32 "
                 "{%0,%1,%2,%3},{%4,%5,%6,%7},{%8,%9},{%0,%1,%2,%3};"
                 : "+f"(d0), "+f"(d1), "+f"(d2), "+f"(d3)
                 : "r"(a0), "r"(a1), "r"(a2), "r"(a3), "r"(b0), "r"(b1));
}
__device__ __forceinline__ void mma_tf32_z(float& d0, float& d1, float& d2, float& d3,
                                           uint32_t a0, uint32_t a1, uint32_t a2, uint32_t a3,
                                           uint32_t b0, uint32_t b1) {
    asm volatile("mma.sync.aligned.m16n8k8.row.col.f32.tf32.tf32.f32 "
                 "{%0,%1,%2,%3},{%4,%5,%6,%7},{%8,%9},{%10,%10,%10,%10};"
                 : "=f"(d0), "=f"(d1), "=f"(d2), "=f"(d3)
                 : "r"(a0), "r"(a1), "r"(a2), "r"(a3), "r"(b0), "r"(b1), "f"(0.f));
}

// ---------------------------------------------------------------------------
// Kernel 1: fused projections with smem-staged weights.
// 256 thr, 8 warps, 2 rows/warp = 16 rows/block, grid 256.
// Weights staged in e-chunks of 32: [a][e_local][k][d] -> conflict-free LDS.128.
// Dynamic smem: ws 48KB + xs/ys 16KB = 64KB.
// ---------------------------------------------------------------------------
#define ECHUNK 32
__global__ __launch_bounds__(256) void proj_kernel(
    const float* __restrict__ x, const float* __restrict__ y,
    const float* __restrict__ l1, const float* __restrict__ l2,
    const float* __restrict__ t1, const float* __restrict__ bl)
{
    extern __shared__ float smem_f[];
    float*  ws  = smem_f;                        // 3*ECHUNK*8*16 = 12288 floats
    float*  xs  = smem_f + 3 * ECHUNK * 128;     // 16*128 = 2048
    float*  ys  = xs + 16 * Edim;                // 2048
    float4* ws4 = reinterpret_cast<float4*>(ws);

    const int tid  = threadIdx.x;
    const int w    = tid >> 5;
    const int lane = tid & 31;
    const int row0 = blockIdx.x * 16;

    // Stage 16 x-rows and 16 y-rows once
    {
        const float4* xg = reinterpret_cast<const float4*>(x + (size_t)row0 * Edim);
        const float4* yg = reinterpret_cast<const float4*>(y + (size_t)row0 * Edim);
        float4* xs4 = reinterpret_cast<float4*>(xs);
        float4* ys4 = reinterpret_cast<float4*>(ys);
        #pragma unroll
        for (int i = 0; i < 2; i++) {
            xs4[tid + i * 256] = xg[tid + i * 256];
            ys4[tid + i * 256] = yg[tid + i * 256];
        }
    }

    const int k  = lane >> 2;      // head-in-batch 0..7
    const int dq = lane & 3;       // d-quad

    const float4* warr[3] = {
        reinterpret_cast<const float4*>(l1),
        reinterpret_cast<const float4*>(t1),
        reinterpret_cast<const float4*>(l2) };

    float4 ka[2], va[2], qa[2];
    #pragma unroll
    for (int r = 0; r < 2; r++) {
        ka[r] = make_float4(0.f,0.f,0.f,0.f);
        va[r] = make_float4(0.f,0.f,0.f,0.f);
        qa[r] = make_float4(0.f,0.f,0.f,0.f);
    }

    for (int e0 = 0; e0 < Edim; e0 += ECHUNK) {
        __syncthreads();
        // Stage weight chunk: ws4[a*1024 + e_local*32 + k*4 + dq]
        #pragma unroll
        for (int ii = 0; ii < 12; ii++) {
            const int i = tid + ii * 256;          // 0..3071
            const int a   = i >> 10;
            const int kk  = (i >> 7) & 7;
            const int f4  = i & 127;               // e_local*4 + dq
            const int el  = f4 >> 2;
            const int dqq = f4 & 3;
            ws4[a * 1024 + el * 32 + kk * 4 + dqq] =
                warr[a][(kk * Edim + e0 + el) * 4 + dqq];
        }
        __syncthreads();

        #pragma unroll 4
        for (int el = 0; el < ECHUNK; el++) {
            const int wi = el * 32 + lane;
            const float4 A  = ws4[wi];
            const float4 C  = ws4[1024 + wi];
            const float4 Qw = ws4[2048 + wi];
            const int e = e0 + el;
            #pragma unroll
            for (int r = 0; r < 2; r++) {
                const float xv = xs[(w * 2 + r) * Edim + e];
                const float yv = ys[(w * 2 + r) * Edim + e];
                ka[r].x += xv * A.x;  ka[r].y += xv * A.y;  ka[r].z += xv * A.z;  ka[r].w += xv * A.w;
                va[r].x += xv * C.x;  va[r].y += xv * C.y;  va[r].z += xv * C.z;  va[r].w += xv * C.w;
                qa[r].x += yv * Qw.x; qa[r].y += yv * Qw.y; qa[r].z += yv * Qw.z; qa[r].w += yv * Qw.w;
            }
        }
    }

    const float4 bb = reinterpret_cast<const float4*>(bl)[k * 4 + dq];
    #pragma unroll
    for (int r = 0; r < 2; r++) {
        ka[r].x += bb.x; ka[r].y += bb.y; ka[r].z += bb.z; ka[r].w += bb.w;
        const int row = row0 + w * 2 + r;
        const int b   = row / Mdim;
        const int m   = row % Mdim;
        const int head = b * Kdim + k;

        reinterpret_cast<float4*>(g_Q)[(((size_t)head * Mdim + m) * Ddim) / 4 + dq] = qa[r];

        {   // K: tf32 hi/lo split, fragment-packed
            const size_t kpb = ((size_t)head * (Mdim / 8) + (m >> 3)) * 128;
            const float kv[4] = {ka[r].x, ka[r].y, ka[r].z, ka[r].w};
            #pragma unroll
            for (int j = 0; j < 4; j++) {
                const float hi = __uint_as_float(to_tf32(kv[j]));
                const float lo = __uint_as_float(to_tf32(kv[j] - hi));
                const size_t off = kpb + (size_t)(4 * (m & 7) + j) * 4 + dq;
                g_K [off] = hi;
                g_K2[off] = lo;
            }
        }
        {   // V: tf32-truncated, fragment-packed
            const size_t vpb = ((size_t)head * (Mdim / 8) + (m >> 3)) * 128;
            const int c = ((m >> 2) & 1) | ((dq >> 1) << 1);
            const float vv[4] = {va[r].x, va[r].y, va[r].z, va[r].w};
            #pragma unroll
            for (int j = 0; j < 4; j++)
                g_V[vpb + (size_t)(16 * (dq & 1) + 4 * j + (m & 3)) * 4 + c] =
                    __uint_as_float(to_tf32(vv[j]));
        }
    }
}

// ---------------------------------------------------------------------------
// Kernel 2: flash attention via 3xTF32 mma, split-K over keys (4 splits).
// Grid (16 qtiles, 16 heads, 4 splits) = 1024 blocks x 4 warps -> ~28 warps/SM.
// Writes additive partials (o, l) — no max tracking, so no rescale needed.
// ---------------------------------------------------------------------------
__global__ __launch_bounds__(128) void flash_kernel()
{
    const int head = blockIdx.y;
    const int sp   = blockIdx.z;
    const int warp = threadIdx.x >> 5;
    const int lane = threadIdx.x & 31;
    const int g = lane >> 2, t = lane & 3;
    const int qb = blockIdx.x * 128 + warp * 32;

    const float sc = 0.25f * 1.4426950408889634f;

    const float* Qh = g_Q + ((size_t)head * Ndim + qb) * Ddim;
    uint32_t qhi[2][8], qlo[2][8];
    #pragma unroll
    for (int f = 0; f < 2; f++) {
        #pragma unroll
        for (int c = 0; c < 2; c++) {
            const float v0 = Qh[(16*f + g    ) * Ddim + t     + 8*c] * sc;
            const float v1 = Qh[(16*f + g + 8) * Ddim + t     + 8*c] * sc;
            const float v2 = Qh[(16*f + g    ) * Ddim + t + 4 + 8*c] * sc;
            const float v3 = Qh[(16*f + g + 8) * Ddim + t + 4 + 8*c] * sc;
            qhi[f][4*c+0] = to_tf32(v0); qlo[f][4*c+0] = to_tf32(v0 - __uint_as_float(qhi[f][4*c+0]));
            qhi[f][4*c+1] = to_tf32(v1); qlo[f][4*c+1] = to_tf32(v1 - __uint_as_float(qhi[f][4*c+1]));
            qhi[f][4*c+2] = to_tf32(v2); qlo[f][4*c+2] = to_tf32(v2 - __uint_as_float(qhi[f][4*c+2]));
            qhi[f][4*c+3] = to_tf32(v3); qlo[f][4*c+3] = to_tf32(v3 - __uint_as_float(qhi[f][4*c+3]));
        }
    }

    float o[2][8];
    float lsum[2][2];
    #pragma unroll
    for (int f = 0; f < 2; f++) {
        #pragma unroll
        for (int i = 0; i < 8; i++) o[f][i] = 0.f;
        lsum[f][0] = 0.f; lsum[f][1] = 0.f;
    }

    const int kb0 = sp * (MCHUNK / 8);
    const int kb1 = kb0 + (MCHUNK / 8);
    const float4* Kp  = reinterpret_cast<const float4*>(g_K ) + (size_t)head * (Mdim / 8) * 32;
    const float4* K2p = reinterpret_cast<const float4*>(g_K2) + (size_t)head * (Mdim / 8) * 32;
    const float4* Vp  = reinterpret_cast<const float4*>(g_V ) + (size_t)head * (Mdim / 8) * 32;

    const int src  = (lane & ~3) | (t >> 1);
    const int src2 = src + 2;
    const bool odd = (t & 1);

    float4 kh = Kp [kb0 * 32 + lane];
    float4 kl = K2p[kb0 * 32 + lane];
    float4 vf = Vp [kb0 * 32 + lane];

    #pragma unroll 2
    for (int kb = kb0; kb < kb1; kb++) {
        float4 kh_n, kl_n, vf_n;
        if (kb + 1 < kb1) {
            kh_n = Kp [(kb + 1) * 32 + lane];
            kl_n = K2p[(kb + 1) * 32 + lane];
            vf_n = Vp [(kb + 1) * 32 + lane];
        }
        const uint32_t bh0 = __float_as_uint(kh.x), bh1 = __float_as_uint(kh.y);
        const uint32_t bh2 = __float_as_uint(kh.z), bh3 = __float_as_uint(kh.w);
        const uint32_t bL0 = __float_as_uint(kl.x), bL1 = __float_as_uint(kl.y);
        const uint32_t bL2 = __float_as_uint(kl.z), bL3 = __float_as_uint(kl.w);
        const uint32_t bv0 = __float_as_uint(vf.x), bv1 = __float_as_uint(vf.y);
        const uint32_t bv2 = __float_as_uint(vf.z), bv3 = __float_as_uint(vf.w);

        #pragma unroll
        for (int f = 0; f < 2; f++) {
            float sA0, sA1, sA2, sA3, sB0, sB1, sB2, sB3;
            mma_tf32_z(sA0, sA1, sA2, sA3, qhi[f][0], qhi[f][1], qhi[f][2], qhi[f][3], bh0, bh1);
            mma_tf32_z(sB0, sB1, sB2, sB3, qhi[f][4], qhi[f][5], qhi[f][6], qhi[f][7], bh2, bh3);
            mma_tf32(sA0, sA1, sA2, sA3, qlo[f][0], qlo[f][1], qlo[f][2], qlo[f][3], bh0, bh1);
            mma_tf32(sB0, sB1, sB2, sB3, qlo[f][4], qlo[f][5], qlo[f][6], qlo[f][7], bh2, bh3);
            mma_tf32(sA0, sA1, sA2, sA3, qhi[f][0], qhi[f][1], qhi[f][2], qhi[f][3], bL0, bL1);
            mma_tf32(sB0, sB1, sB2, sB3, qhi[f][4], qhi[f][5], qhi[f][6], qhi[f][7], bL2, bL3);

            const float p0 = __uint_as_float(to_tf32(ex2f(sA0 + sB0)));
            const float p1 = __uint_as_float(to_tf32(ex2f(sA1 + sB1)));
            const float p2 = __uint_as_float(to_tf32(ex2f(sA2 + sB2)));
            const float p3 = __uint_as_float(to_tf32(ex2f(sA3 + sB3)));
            lsum[f][0] += p0 + p1;
            lsum[f][1] += p2 + p3;

            const float x0 = __shfl_sync(0xffffffffu, p0, src);
            const float x1 = __shfl_sync(0xffffffffu, p1, src);
            const float x2 = __shfl_sync(0xffffffffu, p2, src);
            const float x3 = __shfl_sync(0xffffffffu, p3, src);
            const float y0 = __shfl_sync(0xffffffffu, p0, src2);
            const float y1 = __shfl_sync(0xffffffffu, p1, src2);
            const float y2 = __shfl_sync(0xffffffffu, p2, src2);
            const float y3 = __shfl_sync(0xffffffffu, p3, src2);
            const uint32_t a0 = __float_as_uint(odd ? x1 : x0);
            const uint32_t a1 = __float_as_uint(odd ? x3 : x2);
            const uint32_t a2 = __float_as_uint(odd ? y1 : y0);
            const uint32_t a3 = __float_as_uint(odd ? y3 : y2);

            mma_tf32(o[f][0], o[f][1], o[f][2], o[f][3], a0, a1, a2, a3, bv0, bv1);
            mma_tf32(o[f][4], o[f][5], o[f][6], o[f][7], a0, a1, a2, a3, bv2, bv3);
        }
        kh = kh_n; kl = kl_n; vf = vf_n;
    }

    // Write additive partials
    const size_t pb = ((size_t)head * SPLIT + sp) * Ndim;
    #pragma unroll
    for (int f = 0; f < 2; f++) {
        float l0 = lsum[f][0], l1 = lsum[f][1];
        l0 += __shfl_xor_sync(0xffffffffu, l0, 1);
        l0 += __shfl_xor_sync(0xffffffffu, l0, 2);
        l1 += __shfl_xor_sync(0xffffffffu, l1, 1);
        l1 += __shfl_xor_sync(0xffffffffu, l1, 2);
        const int rlo = qb + 16*f + g;
        const int rhi = rlo + 8;
        if (t == 0) {
            g_Pl[pb + rlo] = l0;
            g_Pl[pb + rhi] = l1;
        }
        #pragma unroll
        for (int c = 0; c < 2; c++) {
            const int d0 = 8 * c + 2 * t;
            *reinterpret_cast<float2*>(g_Po + (pb + rlo) * Ddim + d0) =
                make_float2(o[f][4*c+0], o[f][4*c+1]);
            *reinterpret_cast<float2*>(g_Po + (pb + rhi) * Ddim + d0) =
                make_float2(o[f][4*c+2], o[f][4*c+3]);
        }
    }
}

// ---------------------------------------------------------------------------
// Kernel 2b: combine — plain sums across splits (no rescale), + bias_theta.
// ---------------------------------------------------------------------------
__global__ __launch_bounds__(128) void combine_kernel(const float* __restrict__ bt)
{
    const int head = blockIdx.y;
    const int n    = blockIdx.x * 128 + threadIdx.x;

    float L = 0.f;
    float o[Ddim];
    #pragma unroll
    for (int d = 0; d < Ddim; d++) o[d] = 0.f;

    #pragma unroll
    for (int s = 0; s < SPLIT; s++) {
        const size_t pb = ((size_t)head * SPLIT + s) * Ndim + n;
        L += g_Pl[pb];
        const float4* Pp = reinterpret_cast<const float4*>(g_Po + pb * Ddim);
        #pragma unroll
        for (int i = 0; i < 4; i++) {
            const float4 v = Pp[i];
            o[4*i+0] += v.x; o[4*i+1] += v.y; o[4*i+2] += v.z; o[4*i+3] += v.w;
        }
    }
    const float inv = 1.f / L;

    const int b = head >> 3, k = head & 7;
    float* Op = g_O + (((size_t)b * Ndim + n) * Kdim + k) * Ddim;
    #pragma unroll
    for (int i = 0; i < 4; i++) {
        float4 r;
        r.x = o[4*i+0] * inv + bt[k * Ddim + 4*i + 0];
        r.y = o[4*i+1] * inv + bt[k * Ddim + 4*i + 1];
        r.z = o[4*i+2] * inv + bt[k * Ddim + 4*i + 2];
        r.w = o[4*i+3] * inv + bt[k * Ddim + 4*i + 3];
        reinterpret_cast<float4*>(Op)[i] = r;
    }
}

// ---------------------------------------------------------------------------
// Kernel 3: output projection, 4 rows/block (grid 1024).
// ---------------------------------------------------------------------------
__global__ __launch_bounds__(128) void out_kernel(const float* __restrict__ t2,
                                                  float* __restrict__ out)
{
    __shared__ __align__(16) float orow[4][Kdim * Ddim];
    const int row0 = blockIdx.x * 4;
    const int e = threadIdx.x;

    #pragma unroll
    for (int r = 0; r < 4; r++)
        orow[r][e] = g_O[(size_t)(row0 + r) * (Kdim * Ddim) + e];
    __syncthreads();

    float acc[4];
    #pragma unroll
    for (int r = 0; r < 4; r++) acc[r] = 0.f;

    const float4* t2v = reinterpret_cast<const float4*>(t2);
    #pragma unroll
    for (int k = 0; k < Kdim; k++) {
        const int base = (k * Edim + e) * 4;
        #pragma unroll
        for (int dq = 0; dq < 4; dq++) {
            const float4 wv = t2v[base + dq];
            #pragma unroll
            for (int r = 0; r < 4; r++) {
                const float4 oo = *reinterpret_cast<const float4*>(&orow[r][k * Ddim + dq * 4]);
                acc[r] += wv.x * oo.x + wv.y * oo.y + wv.z * oo.z + wv.w * oo.w;
            }
        }
    }
    #pragma unroll
    for (int r = 0; r < 4; r++)
        out[(size_t)(row0 + r) * Edim + e] = acc[r];
}

extern "C" void kernel_launch(void* const* d_in, const int* in_sizes, int n_in,
                              void* d_out, int out_size)
{
    const float* x  = (const float*)d_in[0];
    const float* y  = (const float*)d_in[1];
    const float* l1 = (const float*)d_in[2];
    const float* l2 = (const float*)d_in[3];
    const float* t1 = (const float*)d_in[4];
    const float* t2 = (const float*)d_in[5];
    const float* bl = (const float*)d_in[6];
    const float* bt = (const float*)d_in[7];

    const int proj_smem = (3 * ECHUNK * 128 + 2 * 16 * Edim) * sizeof(float);  // 64KB
    static bool attr_set = false;
    if (!attr_set) {
        cudaFuncSetAttribute(proj_kernel, cudaFuncAttributeMaxDynamicSharedMemorySize, proj_smem);
        attr_set = true;
    }

    proj_kernel<<<Bdim * Mdim / 16, 256, proj_smem>>>(x, y, l1, l2, t1, bl);
    flash_kernel<<<dim3(Ndim / 128, NHEAD, SPLIT), 128>>>();
    combine_kernel<<<dim3(Ndim / 128, NHEAD), 128>>>(bt);
    out_kernel<<<Bdim * Ndim / 4, 128>>>(t2, (float*)d_out);
}

// round 8
// speedup vs baseline: 2.4075x; 1.5735x over previous
#include <cuda_runtime.h>
#include <cuda_fp16.h>
#include <math.h>
#include <stdint.h>

// Problem dims (fixed)
#define Bdim 2
#define Mdim 2048
#define Ndim 2048
#define Edim 128
#define Kdim 8
#define Ddim 16
#define NHEAD (Bdim * Kdim)
#define SPLIT 4
#define MCHUNK (Mdim / SPLIT)   // 512 keys per split
#define SHIFT 10.0f             // uniform log2-domain logit shift (softmax-invariant)

// Static scratch.
// g_Q : plain [head][n][16] fp32
// g_Kh/g_Kl: fp16 hi/lo of K, packed as m16n8k16 B-fragments
// g_Vh: fp16 V packed as PV B-fragments
// g_W : theta2 fp16 hi/lo packed B-fragments for the output GEMM
// g_O : [b][n][k][d] fp32 ; g_Po/g_Pl: split partials (additive)
__device__ float    g_Q [NHEAD * (size_t)Ndim * Ddim];
__device__ uint32_t g_Kh[NHEAD * (size_t)(Mdim / 16) * 128];
__device__ uint32_t g_Kl[NHEAD * (size_t)(Mdim / 16) * 128];
__device__ uint32_t g_Vh[NHEAD * (size_t)(Mdim / 16) * 128];
__device__ uint4    g_W [8 * 16 * 32];
__device__ float    g_O [Bdim * (size_t)Ndim * Kdim * Ddim];
__device__ float    g_Po[NHEAD * (size_t)SPLIT * Ndim * Ddim];
__device__ float    g_Pl[NHEAD * (size_t)SPLIT * Ndim];

__device__ __forceinline__ float ex2f(float x) {
    float r; asm("ex2.approx.f32 %0, %1;" : "=f"(r) : "f"(x)); return r;
}
__device__ __forceinline__ uint32_t pack_h2(float a, float b) {
    __half2 h = __floats2half2_rn(a, b);
    return *reinterpret_cast<uint32_t*>(&h);
}
__device__ __forceinline__ float2 unpack_h2(uint32_t u) {
    __half2 h = *reinterpret_cast<__half2*>(&u);
    return __half22float2(h);
}
__device__ __forceinline__ uint32_t split_lo(float a, float b, uint32_t hi) {
    float2 hf = unpack_h2(hi);
    return pack_h2(a - hf.x, b - hf.y);
}
// D += A(f16 m16k16) * B(f16 k16n8), fp32 accumulate
__device__ __forceinline__ void mma_f16(float& d0, float& d1, float& d2, float& d3,
                                        uint32_t a0, uint32_t a1, uint32_t a2, uint32_t a3,
                                        uint32_t b0, uint32_t b1) {
    asm volatile("mma.sync.aligned.m16n8k16.row.col.f32.f16.f16.f32 "
                 "{%0,%1,%2,%3},{%4,%5,%6,%7},{%8,%9},{%0,%1,%2,%3};"
                 : "+f"(d0), "+f"(d1), "+f"(d2), "+f"(d3)
                 : "r"(a0), "r"(a1), "r"(a2), "r"(a3), "r"(b0), "r"(b1));
}
__device__ __forceinline__ void mma_f16_z(float& d0, float& d1, float& d2, float& d3,
                                          uint32_t a0, uint32_t a1, uint32_t a2, uint32_t a3,
                                          uint32_t b0, uint32_t b1) {
    asm volatile("mma.sync.aligned.m16n8k16.row.col.f32.f16.f16.f32 "
                 "{%0,%1,%2,%3},{%4,%5,%6,%7},{%8,%9},{%10,%10,%10,%10};"
                 : "=f"(d0), "=f"(d1), "=f"(d2), "=f"(d3)
                 : "r"(a0), "r"(a1), "r"(a2), "r"(a3), "r"(b0), "r"(b1), "f"(0.f));
}

// ---------------------------------------------------------------------------
// Kernel 0: pack theta2 into fp16 hi/lo B-fragments.
// ---------------------------------------------------------------------------
__global__ __launch_bounds__(128) void prep_w(const float* __restrict__ t2)
{
    const int idx  = blockIdx.x * 128 + threadIdx.x;   // 0..4095
    const int kc   = idx >> 9;
    const int et   = (idx >> 5) & 15;
    const int lane = idx & 31;
    const int g = lane >> 2, t = lane & 3;
    const int e = et * 8 + g;

    const float2 wA = *reinterpret_cast<const float2*>(t2 + ((size_t)kc * Edim + e) * Ddim + 2 * t);
    const float2 wB = *reinterpret_cast<const float2*>(t2 + ((size_t)kc * Edim + e) * Ddim + 2 * t + 8);
    const uint32_t h0 = pack_h2(wA.x, wA.y), l0 = split_lo(wA.x, wA.y, h0);
    const uint32_t h1 = pack_h2(wB.x, wB.y), l1 = split_lo(wB.x, wB.y, h1);
    g_W[(kc * 16 + et) * 32 + lane] = make_uint4(h0, h1, l0, l1);
}

// ---------------------------------------------------------------------------
// Kernel 1: fused projections (smem-staged weights), writing fp16
// fragment-packed K(hi/lo) and V layouts.
// ---------------------------------------------------------------------------
#define ECHUNK 32
__global__ __launch_bounds__(256) void proj_kernel(
    const float* __restrict__ x, const float* __restrict__ y,
    const float* __restrict__ l1, const float* __restrict__ l2,
    const float* __restrict__ t1, const float* __restrict__ bl)
{
    extern __shared__ float smem_f[];
    float*  ws  = smem_f;
    float*  xs  = smem_f + 3 * ECHUNK * 128;
    float*  ys  = xs + 16 * Edim;
    float4* ws4 = reinterpret_cast<float4*>(ws);

    const int tid  = threadIdx.x;
    const int w    = tid >> 5;
    const int lane = tid & 31;
    const int row0 = blockIdx.x * 16;

    {
        const float4* xg = reinterpret_cast<const float4*>(x + (size_t)row0 * Edim);
        const float4* yg = reinterpret_cast<const float4*>(y + (size_t)row0 * Edim);
        float4* xs4 = reinterpret_cast<float4*>(xs);
        float4* ys4 = reinterpret_cast<float4*>(ys);
        #pragma unroll
        for (int i = 0; i < 2; i++) {
            xs4[tid + i * 256] = xg[tid + i * 256];
            ys4[tid + i * 256] = yg[tid + i * 256];
        }
    }

    const int k  = lane >> 2;
    const int dq = lane & 3;

    const float4* warr[3] = {
        reinterpret_cast<const float4*>(l1),
        reinterpret_cast<const float4*>(t1),
        reinterpret_cast<const float4*>(l2) };

    float4 ka[2], va[2], qa[2];
    #pragma unroll
    for (int r = 0; r < 2; r++) {
        ka[r] = make_float4(0.f,0.f,0.f,0.f);
        va[r] = make_float4(0.f,0.f,0.f,0.f);
        qa[r] = make_float4(0.f,0.f,0.f,0.f);
    }

    for (int e0 = 0; e0 < Edim; e0 += ECHUNK) {
        __syncthreads();
        #pragma unroll
        for (int ii = 0; ii < 12; ii++) {
            const int i = tid + ii * 256;
            const int a   = i >> 10;
            const int kk  = (i >> 7) & 7;
            const int f4  = i & 127;
            const int el  = f4 >> 2;
            const int dqq = f4 & 3;
            ws4[a * 1024 + el * 32 + kk * 4 + dqq] =
                warr[a][(kk * Edim + e0 + el) * 4 + dqq];
        }
        __syncthreads();

        #pragma unroll 4
        for (int el = 0; el < ECHUNK; el++) {
            const int wi = el * 32 + lane;
            const float4 A  = ws4[wi];
            const float4 C  = ws4[1024 + wi];
            const float4 Qw = ws4[2048 + wi];
            const int e = e0 + el;
            #pragma unroll
            for (int r = 0; r < 2; r++) {
                const float xv = xs[(w * 2 + r) * Edim + e];
                const float yv = ys[(w * 2 + r) * Edim + e];
                ka[r].x += xv * A.x;  ka[r].y += xv * A.y;  ka[r].z += xv * A.z;  ka[r].w += xv * A.w;
                va[r].x += xv * C.x;  va[r].y += xv * C.y;  va[r].z += xv * C.z;  va[r].w += xv * C.w;
                qa[r].x += yv * Qw.x; qa[r].y += yv * Qw.y; qa[r].z += yv * Qw.z; qa[r].w += yv * Qw.w;
            }
        }
    }

    const float4 bb = reinterpret_cast<const float4*>(bl)[k * 4 + dq];
    const int rowE = row0 + w * 2;            // even row (r=0)
    const int b    = rowE / Mdim;
    const int head = b * Kdim + k;

    #pragma unroll
    for (int r = 0; r < 2; r++) {
        ka[r].x += bb.x; ka[r].y += bb.y; ka[r].z += bb.z; ka[r].w += bb.w;
        const int m = (rowE + r) % Mdim;

        // Q plain fp32
        reinterpret_cast<float4*>(g_Q)[(((size_t)head * Mdim + m) * Ddim) / 4 + dq] = qa[r];

        // K hi/lo fp16, fragment packed
        const size_t b16 = (size_t)head * (Mdim / 16) + (m >> 4);
        const int grp = (m >> 3) & 1, g8 = m & 7;
        const uint32_t h01 = pack_h2(ka[r].x, ka[r].y);
        const uint32_t l01 = split_lo(ka[r].x, ka[r].y, h01);
        const uint32_t h23 = pack_h2(ka[r].z, ka[r].w);
        const uint32_t l23 = split_lo(ka[r].z, ka[r].w, h23);
        const int pp0 = 2 * dq, pp1 = 2 * dq + 1;
        const size_t i0 = (b16 * 32 + 4 * g8 + (pp0 & 3)) * 4 + grp * 2 + (pp0 >> 2);
        const size_t i1 = (b16 * 32 + 4 * g8 + (pp1 & 3)) * 4 + grp * 2 + (pp1 >> 2);
        g_Kh[i0] = h01;  g_Kl[i0] = l01;
        g_Kh[i1] = h23;  g_Kl[i1] = l23;
    }

    // V fp16, fragment packed: pairs over (even,odd) adjacent keys
    {
        const int m0 = rowE % Mdim;
        const size_t vb16 = (size_t)head * (Mdim / 16) + (m0 >> 4);
        const int kp = (m0 >> 1) & 7;
        const float ve[4] = {va[0].x, va[0].y, va[0].z, va[0].w};
        const float vo[4] = {va[1].x, va[1].y, va[1].z, va[1].w};
        #pragma unroll
        for (int j = 0; j < 4; j++) {
            const int d = 4 * dq + j;
            const uint32_t u = pack_h2(ve[j], vo[j]);
            g_Vh[(vb16 * 32 + 4 * (d & 7) + (kp & 3)) * 4 + ((kp >> 2) | ((d >> 3) << 1))] = u;
        }
    }
}

// ---------------------------------------------------------------------------
// Kernel 2: flash attention via fp16 hi/lo mma.m16n8k16, split-K (4 splits).
// p = 2^(s - SHIFT) keeps fp16 safe (overflow needs a 10-sigma logit).
// l sums the fp16-ROUNDED p so l and PV weights are bit-identical.
// ---------------------------------------------------------------------------
__global__ __launch_bounds__(128) void flash_kernel()
{
    const int head = blockIdx.y;
    const int sp   = blockIdx.z;
    const int warp = threadIdx.x >> 5;
    const int lane = threadIdx.x & 31;
    const int g = lane >> 2, t = lane & 3;
    const int qb = blockIdx.x * 128 + warp * 32;

    const float sc = 0.25f * 1.4426950408889634f;

    uint32_t qhi[2][4], qlo[2][4];
    #pragma unroll
    for (int f = 0; f < 2; f++) {
        const float* Qr = g_Q + ((size_t)head * Ndim + qb + 16 * f) * Ddim;
        const float2 v0 = *reinterpret_cast<const float2*>(Qr + (g    ) * Ddim + 2 * t);
        const float2 v1 = *reinterpret_cast<const float2*>(Qr + (g + 8) * Ddim + 2 * t);
        const float2 v2 = *reinterpret_cast<const float2*>(Qr + (g    ) * Ddim + 2 * t + 8);
        const float2 v3 = *reinterpret_cast<const float2*>(Qr + (g + 8) * Ddim + 2 * t + 8);
        qhi[f][0] = pack_h2(v0.x * sc, v0.y * sc); qlo[f][0] = split_lo(v0.x * sc, v0.y * sc, qhi[f][0]);
        qhi[f][1] = pack_h2(v1.x * sc, v1.y * sc); qlo[f][1] = split_lo(v1.x * sc, v1.y * sc, qhi[f][1]);
        qhi[f][2] = pack_h2(v2.x * sc, v2.y * sc); qlo[f][2] = split_lo(v2.x * sc, v2.y * sc, qhi[f][2]);
        qhi[f][3] = pack_h2(v3.x * sc, v3.y * sc); qlo[f][3] = split_lo(v3.x * sc, v3.y * sc, qhi[f][3]);
    }

    float o[2][8];
    float lsum[2][2];
    #pragma unroll
    for (int f = 0; f < 2; f++) {
        #pragma unroll
        for (int i = 0; i < 8; i++) o[f][i] = 0.f;
        lsum[f][0] = 0.f; lsum[f][1] = 0.f;
    }

    const int kb0 = sp * (MCHUNK / 16);
    const int nkb = MCHUNK / 16;
    const uint4* Khp = reinterpret_cast<const uint4*>(g_Kh) + (size_t)head * (Mdim / 16) * 32;
    const uint4* Klp = reinterpret_cast<const uint4*>(g_Kl) + (size_t)head * (Mdim / 16) * 32;
    const uint4* Vp  = reinterpret_cast<const uint4*>(g_Vh) + (size_t)head * (Mdim / 16) * 32;

    uint4 kh = Khp[kb0 * 32 + lane];
    uint4 kl = Klp[kb0 * 32 + lane];
    uint4 vv = Vp [kb0 * 32 + lane];

    #pragma unroll 2
    for (int i = 0; i < nkb; i++) {
        const int kb = kb0 + i;
        uint4 kh_n, kl_n, vv_n;
        if (i + 1 < nkb) {
            kh_n = Khp[(kb + 1) * 32 + lane];
            kl_n = Klp[(kb + 1) * 32 + lane];
            vv_n = Vp [(kb + 1) * 32 + lane];
        }

        #pragma unroll
        for (int f = 0; f < 2; f++) {
            float s0, s1, s2, s3;
            mma_f16_z(s0, s1, s2, s3, qhi[f][0], qhi[f][1], qhi[f][2], qhi[f][3], kh.x, kh.y);
            mma_f16  (s0, s1, s2, s3, qlo[f][0], qlo[f][1], qlo[f][2], qlo[f][3], kh.x, kh.y);
            mma_f16  (s0, s1, s2, s3, qhi[f][0], qhi[f][1], qhi[f][2], qhi[f][3], kl.x, kl.y);
            float u0, u1, u2, u3;
            mma_f16_z(u0, u1, u2, u3, qhi[f][0], qhi[f][1], qhi[f][2], qhi[f][3], kh.z, kh.w);
            mma_f16  (u0, u1, u2, u3, qlo[f][0], qlo[f][1], qlo[f][2], qlo[f][3], kh.z, kh.w);
            mma_f16  (u0, u1, u2, u3, qhi[f][0], qhi[f][1], qhi[f][2], qhi[f][3], kl.z, kl.w);

            // shifted exp (softmax-invariant); pack to fp16 A-fragment
            const uint32_t a0 = pack_h2(ex2f(s0 - SHIFT), ex2f(s1 - SHIFT));
            const uint32_t a1 = pack_h2(ex2f(s2 - SHIFT), ex2f(s3 - SHIFT));
            const uint32_t a2 = pack_h2(ex2f(u0 - SHIFT), ex2f(u1 - SHIFT));
            const uint32_t a3 = pack_h2(ex2f(u2 - SHIFT), ex2f(u3 - SHIFT));

            // sum the fp16-rounded weights (bit-identical to what PV uses)
            const float2 f0 = unpack_h2(a0), f1 = unpack_h2(a1);
            const float2 f2 = unpack_h2(a2), f3 = unpack_h2(a3);
            lsum[f][0] += (f0.x + f0.y) + (f2.x + f2.y);   // rows g
            lsum[f][1] += (f1.x + f1.y) + (f3.x + f3.y);   // rows g+8

            mma_f16(o[f][0], o[f][1], o[f][2], o[f][3], a0, a1, a2, a3, vv.x, vv.y);
            mma_f16(o[f][4], o[f][5], o[f][6], o[f][7], a0, a1, a2, a3, vv.z, vv.w);
        }
        kh = kh_n; kl = kl_n; vv = vv_n;
    }

    const size_t pb = ((size_t)head * SPLIT + sp) * Ndim;
    #pragma unroll
    for (int f = 0; f < 2; f++) {
        float l0 = lsum[f][0], l1 = lsum[f][1];
        l0 += __shfl_xor_sync(0xffffffffu, l0, 1);
        l0 += __shfl_xor_sync(0xffffffffu, l0, 2);
        l1 += __shfl_xor_sync(0xffffffffu, l1, 1);
        l1 += __shfl_xor_sync(0xffffffffu, l1, 2);
        const int rlo = qb + 16*f + g;
        const int rhi = rlo + 8;
        if (t == 0) {
            g_Pl[pb + rlo] = l0;
            g_Pl[pb + rhi] = l1;
        }
        #pragma unroll
        for (int c = 0; c < 2; c++) {
            const int d0 = 8 * c + 2 * t;
            *reinterpret_cast<float2*>(g_Po + (pb + rlo) * Ddim + d0) =
                make_float2(o[f][4*c+0], o[f][4*c+1]);
            *reinterpret_cast<float2*>(g_Po + (pb + rhi) * Ddim + d0) =
                make_float2(o[f][4*c+2], o[f][4*c+3]);
        }
    }
}

// ---------------------------------------------------------------------------
// Kernel 2b: combine — plain sums across splits, + bias_theta.
// ---------------------------------------------------------------------------
__global__ __launch_bounds__(128) void combine_kernel(const float* __restrict__ bt)
{
    const int head = blockIdx.y;
    const int n    = blockIdx.x * 128 + threadIdx.x;

    float L = 0.f;
    float o[Ddim];
    #pragma unroll
    for (int d = 0; d < Ddim; d++) o[d] = 0.f;

    #pragma unroll
    for (int s = 0; s < SPLIT; s++) {
        const size_t pb = ((size_t)head * SPLIT + s) * Ndim + n;
        L += g_Pl[pb];
        const float4* Pp = reinterpret_cast<const float4*>(g_Po + pb * Ddim);
        #pragma unroll
        for (int i = 0; i < 4; i++) {
            const float4 v = Pp[i];
            o[4*i+0] += v.x; o[4*i+1] += v.y; o[4*i+2] += v.z; o[4*i+3] += v.w;
        }
    }
    const float inv = 1.f / L;

    const int b = head >> 3, k = head & 7;
    float* Op = g_O + (((size_t)b * Ndim + n) * Kdim + k) * Ddim;
    #pragma unroll
    for (int i = 0; i < 4; i++) {
        float4 r;
        r.x = o[4*i+0] * inv + bt[k * Ddim + 4*i + 0];
        r.y = o[4*i+1] * inv + bt[k * Ddim + 4*i + 1];
        r.z = o[4*i+2] * inv + bt[k * Ddim + 4*i + 2];
        r.w = o[4*i+3] * inv + bt[k * Ddim + 4*i + 3];
        reinterpret_cast<float4*>(Op)[i] = r;
    }
}

// ---------------------------------------------------------------------------
// Kernel 3: output projection as fp16 hi/lo tensor-core GEMM.
// ---------------------------------------------------------------------------
__global__ __launch_bounds__(128) void out_kernel(float* __restrict__ out)
{
    const int row0 = blockIdx.x * 16;
    const int warp = threadIdx.x >> 5;
    const int lane = threadIdx.x & 31;
    const int g = lane >> 2, t = lane & 3;

    float acc[4][4];
    #pragma unroll
    for (int e4 = 0; e4 < 4; e4++)
        #pragma unroll
        for (int i = 0; i < 4; i++) acc[e4][i] = 0.f;

    const float* Orl = g_O + (size_t)(row0 + g    ) * 128;
    const float* Orh = g_O + (size_t)(row0 + g + 8) * 128;

    #pragma unroll
    for (int kc = 0; kc < 8; kc++) {
        const float2 xA = *reinterpret_cast<const float2*>(Orl + kc * 16 + 2 * t);
        const float2 yA = *reinterpret_cast<const float2*>(Orh + kc * 16 + 2 * t);
        const float2 xB = *reinterpret_cast<const float2*>(Orl + kc * 16 + 2 * t + 8);
        const float2 yB = *reinterpret_cast<const float2*>(Orh + kc * 16 + 2 * t + 8);
        const uint32_t ah0 = pack_h2(xA.x, xA.y), al0 = split_lo(xA.x, xA.y, ah0);
        const uint32_t ah1 = pack_h2(yA.x, yA.y), al1 = split_lo(yA.x, yA.y, ah1);
        const uint32_t ah2 = pack_h2(xB.x, xB.y), al2 = split_lo(xB.x, xB.y, ah2);
        const uint32_t ah3 = pack_h2(yB.x, yB.y), al3 = split_lo(yB.x, yB.y, ah3);

        #pragma unroll
        for (int e4 = 0; e4 < 4; e4++) {
            const uint4 wv = g_W[(kc * 16 + (warp * 4 + e4)) * 32 + lane];
            mma_f16(acc[e4][0], acc[e4][1], acc[e4][2], acc[e4][3], ah0, ah1, ah2, ah3, wv.x, wv.y);
            mma_f16(acc[e4][0], acc[e4][1], acc[e4][2], acc[e4][3], al0, al1, al2, al3, wv.x, wv.y);
            mma_f16(acc[e4][0], acc[e4][1], acc[e4][2], acc[e4][3], ah0, ah1, ah2, ah3, wv.z, wv.w);
        }
    }

    #pragma unroll
    for (int e4 = 0; e4 < 4; e4++) {
        const int e0 = (warp * 4 + e4) * 8 + 2 * t;
        *reinterpret_cast<float2*>(out + (size_t)(row0 + g    ) * Edim + e0) =
            make_float2(acc[e4][0], acc[e4][1]);
        *reinterpret_cast<float2*>(out + (size_t)(row0 + g + 8) * Edim + e0) =
            make_float2(acc[e4][2], acc[e4][3]);
    }
}

extern "C" void kernel_launch(void* const* d_in, const int* in_sizes, int n_in,
                              void* d_out, int out_size)
{
    const float* x  = (const float*)d_in[0];
    const float* y  = (const float*)d_in[1];
    const float* l1 = (const float*)d_in[2];
    const float* l2 = (const float*)d_in[3];
    const float* t1 = (const float*)d_in[4];
    const float* t2 = (const float*)d_in[5];
    const float* bl = (const float*)d_in[6];
    const float* bt = (const float*)d_in[7];

    const int proj_smem = (3 * ECHUNK * 128 + 2 * 16 * Edim) * sizeof(float);
    static bool attr_set = false;
    if (!attr_set) {
        cudaFuncSetAttribute(proj_kernel, cudaFuncAttributeMaxDynamicSharedMemorySize, proj_smem);
        attr_set = true;
    }

    prep_w<<<32, 128>>>(t2);
    proj_kernel<<<Bdim * Mdim / 16, 256, proj_smem>>>(x, y, l1, l2, t1, bl);
    flash_kernel<<<dim3(Ndim / 128, NHEAD, SPLIT), 128>>>();
    combine_kernel<<<dim3(Ndim / 128, NHEAD), 128>>>(bt);
    out_kernel<<<Bdim * Ndim / 16, 128>>>((float*)d_out);
}

// round 9
// speedup vs baseline: 2.8853x; 1.1984x over previous
#include <cuda_runtime.h>
#include <cuda_fp16.h>
#include <math.h>
#include <stdint.h>

// Problem dims (fixed)
#define Bdim 2
#define Mdim 2048
#define Ndim 2048
#define Edim 128
#define Kdim 8
#define Ddim 16
#define NHEAD (Bdim * Kdim)
#define SPLIT 4
#define MCHUNK (Mdim / SPLIT)   // 512 keys per split
#define SHIFT 10.0f             // uniform log2-domain logit shift (softmax-invariant)

// Static scratch (all fragment-packed, uint4 = one warp-lane's fragment piece).
// g_Qh/g_Ql: Q as fp16 hi/lo m16n8k16 A-fragments, pre-scaled by 0.25*log2(e)
// g_Kh/g_Kl: K as fp16 hi/lo QK^T B-fragments
// g_Vh     : V as fp16 PV B-fragments
// g_WF     : proj weights (l1,t1,l2*sc) as hi/lo B-fragments
// g_W      : theta2 hi/lo B-fragments for the output GEMM
// g_O      : [b][n][k][d] fp32 ; g_Po/g_Pl: split partials (additive)
__device__ uint4 g_Qh[NHEAD * (size_t)(Ndim / 16) * 32];
__device__ uint4 g_Ql[NHEAD * (size_t)(Ndim / 16) * 32];
__device__ uint4 g_Kh[NHEAD * (size_t)(Mdim / 16) * 32];
__device__ uint4 g_Kl[NHEAD * (size_t)(Mdim / 16) * 32];
__device__ uint4 g_Vh[NHEAD * (size_t)(Mdim / 16) * 32];
__device__ uint4 g_WF[3 * 8 * 8 * 2 * 32];
__device__ uint4 g_W [8 * 16 * 32];
__device__ float g_O [Bdim * (size_t)Ndim * Kdim * Ddim];
__device__ float g_Po[NHEAD * (size_t)SPLIT * Ndim * Ddim];
__device__ float g_Pl[NHEAD * (size_t)SPLIT * Ndim];

__device__ __forceinline__ float ex2f(float x) {
    float r; asm("ex2.approx.f32 %0, %1;" : "=f"(r) : "f"(x)); return r;
}
__device__ __forceinline__ uint32_t pack_h2(float a, float b) {
    __half2 h = __floats2half2_rn(a, b);
    return *reinterpret_cast<uint32_t*>(&h);
}
__device__ __forceinline__ float2 unpack_h2(uint32_t u) {
    __half2 h = *reinterpret_cast<__half2*>(&u);
    return __half22float2(h);
}
__device__ __forceinline__ uint32_t split_lo(float a, float b, uint32_t hi) {
    float2 hf = unpack_h2(hi);
    return pack_h2(a - hf.x, b - hf.y);
}
__device__ __forceinline__ uint32_t movm_t(uint32_t s) {
    uint32_t d;
    asm("movmatrix.sync.aligned.m8n8.trans.b16 %0, %1;" : "=r"(d) : "r"(s));
    return d;
}
// D += A(f16 m16k16) * B(f16 k16n8), fp32 accumulate
__device__ __forceinline__ void mma_f16(float& d0, float& d1, float& d2, float& d3,
                                        uint32_t a0, uint32_t a1, uint32_t a2, uint32_t a3,
                                        uint32_t b0, uint32_t b1) {
    asm volatile("mma.sync.aligned.m16n8k16.row.col.f32.f16.f16.f32 "
                 "{%0,%1,%2,%3},{%4,%5,%6,%7},{%8,%9},{%0,%1,%2,%3};"
                 : "+f"(d0), "+f"(d1), "+f"(d2), "+f"(d3)
                 : "r"(a0), "r"(a1), "r"(a2), "r"(a3), "r"(b0), "r"(b1));
}
__device__ __forceinline__ void mma_f16_z(float& d0, float& d1, float& d2, float& d3,
                                          uint32_t a0, uint32_t a1, uint32_t a2, uint32_t a3,
                                          uint32_t b0, uint32_t b1) {
    asm volatile("mma.sync.aligned.m16n8k16.row.col.f32.f16.f16.f32 "
                 "{%0,%1,%2,%3},{%4,%5,%6,%7},{%8,%9},{%10,%10,%10,%10};"
                 : "=f"(d0), "=f"(d1), "=f"(d2), "=f"(d3)
                 : "r"(a0), "r"(a1), "r"(a2), "r"(a3), "r"(b0), "r"(b1), "f"(0.f));
}

// ---------------------------------------------------------------------------
// Kernel 0a: pack theta2 into fp16 hi/lo B-fragments (output GEMM).
// ---------------------------------------------------------------------------
__global__ __launch_bounds__(128) void prep_w(const float* __restrict__ t2)
{
    const int idx  = blockIdx.x * 128 + threadIdx.x;   // 0..4095
    const int kc   = idx >> 9;
    const int et   = (idx >> 5) & 15;
    const int lane = idx & 31;
    const int g = lane >> 2, t = lane & 3;
    const int e = et * 8 + g;

    const float2 wA = *reinterpret_cast<const float2*>(t2 + ((size_t)kc * Edim + e) * Ddim + 2 * t);
    const float2 wB = *reinterpret_cast<const float2*>(t2 + ((size_t)kc * Edim + e) * Ddim + 2 * t + 8);
    const uint32_t h0 = pack_h2(wA.x, wA.y), l0 = split_lo(wA.x, wA.y, h0);
    const uint32_t h1 = pack_h2(wB.x, wB.y), l1 = split_lo(wB.x, wB.y, h1);
    g_W[(kc * 16 + et) * 32 + lane] = make_uint4(h0, h1, l0, l1);
}

// ---------------------------------------------------------------------------
// Kernel 0b: pack proj weights (l1, t1, l2) into hi/lo B-fragments.
// B-frag for e-chunk c, n-tile nt: thread (g,t): b0 = W[e=c*16+2t(,+1)][d=nt*8+g],
// b1 = W[e=c*16+2t+8(,+9)][d]. l2 pre-scaled by 0.25*log2(e).
// ---------------------------------------------------------------------------
__global__ __launch_bounds__(128) void prep_proj_w(
    const float* __restrict__ l1, const float* __restrict__ t1, const float* __restrict__ l2)
{
    const int idx  = blockIdx.x * 128 + threadIdx.x;   // 0..12287
    const int lane = idx & 31;
    const int nt   = (idx >> 5) & 1;
    const int c    = (idx >> 6) & 7;
    const int k    = (idx >> 9) & 7;
    const int a    = idx >> 12;                        // 0=l1(K) 1=t1(V) 2=l2(Q)
    const int g = lane >> 2, t = lane & 3;

    const float* W = (a == 0) ? l1 : (a == 1) ? t1 : l2;
    const float s  = (a == 2) ? (0.25f * 1.4426950408889634f) : 1.0f;
    const int d  = nt * 8 + g;
    const int e0 = c * 16 + 2 * t;

    const float w00 = W[((size_t)k * Edim + e0    ) * Ddim + d] * s;
    const float w01 = W[((size_t)k * Edim + e0 + 1) * Ddim + d] * s;
    const float w10 = W[((size_t)k * Edim + e0 + 8) * Ddim + d] * s;
    const float w11 = W[((size_t)k * Edim + e0 + 9) * Ddim + d] * s;
    const uint32_t h0 = pack_h2(w00, w01), lo0 = split_lo(w00, w01, h0);
    const uint32_t h1 = pack_h2(w10, w11), lo1 = split_lo(w10, w11, h1);
    g_WF[((a * 8 + k) * 8 + c) * 64 + nt * 32 + lane] = make_uint4(h0, h1, lo0, lo1);
}

// ---------------------------------------------------------------------------
// Kernel 1: projections as fp16 hi/lo MMA (3-pass Dekker).
// Warp = one 16-row tile; blockIdx.y = head pair; blockIdx.z: 0=K,V(x) 1=Q(y).
// Proj C-fragments map register-exactly onto the flash fragment layouts:
//   K: pack(c0,c1)/(c2,c3) -> QK^T B-frag ; Q: same pairs -> A-frag ;
//   V: movmatrix.trans of packed pairs -> PV B-frag.
// ---------------------------------------------------------------------------
__global__ __launch_bounds__(128) void proj_mma(
    const float* __restrict__ x, const float* __restrict__ y,
    const float* __restrict__ bl)
{
    const int warp = threadIdx.x >> 5;
    const int lane = threadIdx.x & 31;
    const int g = lane >> 2, t = lane & 3;
    const int tile = blockIdx.x * 4 + warp;     // 0..255 (16-row tiles over 4096 rows)
    const int hp   = blockIdx.y;                // head pair 0..3
    const bool isQ = (blockIdx.z != 0);
    const int row0 = tile * 16;
    const int b    = row0 >> 11;
    const int m0   = row0 & (Mdim - 1);

    // Load A-fragments (x or y rows), hi/lo split
    const float* src = isQ ? y : x;
    uint32_t ahi[8][4], alo[8][4];
    #pragma unroll
    for (int c = 0; c < 8; c++) {
        const float* base = src + (size_t)row0 * Edim + c * 16;
        const float2 v0 = *reinterpret_cast<const float2*>(base + (g    ) * Edim + 2 * t);
        const float2 v1 = *reinterpret_cast<const float2*>(base + (g + 8) * Edim + 2 * t);
        const float2 v2 = *reinterpret_cast<const float2*>(base + (g    ) * Edim + 2 * t + 8);
        const float2 v3 = *reinterpret_cast<const float2*>(base + (g + 8) * Edim + 2 * t + 8);
        ahi[c][0] = pack_h2(v0.x, v0.y); alo[c][0] = split_lo(v0.x, v0.y, ahi[c][0]);
        ahi[c][1] = pack_h2(v1.x, v1.y); alo[c][1] = split_lo(v1.x, v1.y, ahi[c][1]);
        ahi[c][2] = pack_h2(v2.x, v2.y); alo[c][2] = split_lo(v2.x, v2.y, ahi[c][2]);
        ahi[c][3] = pack_h2(v3.x, v3.y); alo[c][3] = split_lo(v3.x, v3.y, ahi[c][3]);
    }

    #pragma unroll
    for (int hh = 0; hh < 2; hh++) {
        const int k = hp * 2 + hh;
        const int head = b * Kdim + k;
        const size_t oidx = ((size_t)head * (Mdim / 16) + (m0 >> 4)) * 32 + lane;

        if (!isQ) {
            float cK[2][4], cV[2][4];
            #pragma unroll
            for (int nt = 0; nt < 2; nt++)
                #pragma unroll
                for (int i = 0; i < 4; i++) { cK[nt][i] = 0.f; cV[nt][i] = 0.f; }

            #pragma unroll
            for (int c = 0; c < 8; c++) {
                #pragma unroll
                for (int nt = 0; nt < 2; nt++) {
                    const uint4 wK = g_WF[((0 * 8 + k) * 8 + c) * 64 + nt * 32 + lane];
                    mma_f16(cK[nt][0], cK[nt][1], cK[nt][2], cK[nt][3],
                            ahi[c][0], ahi[c][1], ahi[c][2], ahi[c][3], wK.x, wK.y);
                    mma_f16(cK[nt][0], cK[nt][1], cK[nt][2], cK[nt][3],
                            alo[c][0], alo[c][1], alo[c][2], alo[c][3], wK.x, wK.y);
                    mma_f16(cK[nt][0], cK[nt][1], cK[nt][2], cK[nt][3],
                            ahi[c][0], ahi[c][1], ahi[c][2], ahi[c][3], wK.z, wK.w);
                    const uint4 wV = g_WF[((1 * 8 + k) * 8 + c) * 64 + nt * 32 + lane];
                    mma_f16(cV[nt][0], cV[nt][1], cV[nt][2], cV[nt][3],
                            ahi[c][0], ahi[c][1], ahi[c][2], ahi[c][3], wV.x, wV.y);
                    mma_f16(cV[nt][0], cV[nt][1], cV[nt][2], cV[nt][3],
                            alo[c][0], alo[c][1], alo[c][2], alo[c][3], wV.x, wV.y);
                    mma_f16(cV[nt][0], cV[nt][1], cV[nt][2], cV[nt][3],
                            ahi[c][0], ahi[c][1], ahi[c][2], ahi[c][3], wV.z, wV.w);
                }
            }

            // bias_lambda into K (cols d = nt*8 + 2t, 2t+1; same for both row groups)
            const float2 bl0 = *reinterpret_cast<const float2*>(bl + k * Ddim + 2 * t);
            const float2 bl1 = *reinterpret_cast<const float2*>(bl + k * Ddim + 8 + 2 * t);
            cK[0][0] += bl0.x; cK[0][1] += bl0.y; cK[0][2] += bl0.x; cK[0][3] += bl0.y;
            cK[1][0] += bl1.x; cK[1][1] += bl1.y; cK[1][2] += bl1.x; cK[1][3] += bl1.y;

            // K -> QK^T B-fragments, hi/lo
            uint4 kh, kl;
            kh.x = pack_h2(cK[0][0], cK[0][1]); kl.x = split_lo(cK[0][0], cK[0][1], kh.x);
            kh.y = pack_h2(cK[1][0], cK[1][1]); kl.y = split_lo(cK[1][0], cK[1][1], kh.y);
            kh.z = pack_h2(cK[0][2], cK[0][3]); kl.z = split_lo(cK[0][2], cK[0][3], kh.z);
            kh.w = pack_h2(cK[1][2], cK[1][3]); kl.w = split_lo(cK[1][2], cK[1][3], kh.w);
            g_Kh[oidx] = kh;
            g_Kl[oidx] = kl;

            // V -> PV B-fragments via movmatrix transpose of each 8x8 tile
            uint4 vv;
            vv.x = movm_t(pack_h2(cV[0][0], cV[0][1]));   // keys 0-7 , d 0-7
            vv.y = movm_t(pack_h2(cV[0][2], cV[0][3]));   // keys 8-15, d 0-7
            vv.z = movm_t(pack_h2(cV[1][0], cV[1][1]));   // keys 0-7 , d 8-15
            vv.w = movm_t(pack_h2(cV[1][2], cV[1][3]));   // keys 8-15, d 8-15
            g_Vh[oidx] = vv;
        } else {
            float cQ[2][4];
            #pragma unroll
            for (int nt = 0; nt < 2; nt++)
                #pragma unroll
                for (int i = 0; i < 4; i++) cQ[nt][i] = 0.f;

            #pragma unroll
            for (int c = 0; c < 8; c++) {
                #pragma unroll
                for (int nt = 0; nt < 2; nt++) {
                    const uint4 wQ = g_WF[((2 * 8 + k) * 8 + c) * 64 + nt * 32 + lane];
                    mma_f16(cQ[nt][0], cQ[nt][1], cQ[nt][2], cQ[nt][3],
                            ahi[c][0], ahi[c][1], ahi[c][2], ahi[c][3], wQ.x, wQ.y);
                    mma_f16(cQ[nt][0], cQ[nt][1], cQ[nt][2], cQ[nt][3],
                            alo[c][0], alo[c][1], alo[c][2], alo[c][3], wQ.x, wQ.y);
                    mma_f16(cQ[nt][0], cQ[nt][1], cQ[nt][2], cQ[nt][3],
                            ahi[c][0], ahi[c][1], ahi[c][2], ahi[c][3], wQ.z, wQ.w);
                }
            }
            // Q -> A-fragments (a0..a3), hi/lo
            uint4 qh, ql;
            qh.x = pack_h2(cQ[0][0], cQ[0][1]); ql.x = split_lo(cQ[0][0], cQ[0][1], qh.x);
            qh.y = pack_h2(cQ[0][2], cQ[0][3]); ql.y = split_lo(cQ[0][2], cQ[0][3], qh.y);
            qh.z = pack_h2(cQ[1][0], cQ[1][1]); ql.z = split_lo(cQ[1][0], cQ[1][1], qh.z);
            qh.w = pack_h2(cQ[1][2], cQ[1][3]); ql.w = split_lo(cQ[1][2], cQ[1][3], qh.w);
            g_Qh[oidx] = qh;
            g_Ql[oidx] = ql;
        }
    }
}

// ---------------------------------------------------------------------------
// Kernel 2: flash attention via fp16 hi/lo mma.m16n8k16, split-K (4 splits).
// Q loaded directly as packed A-fragments. p = 2^(s - SHIFT).
// ---------------------------------------------------------------------------
__global__ __launch_bounds__(128) void flash_kernel()
{
    const int head = blockIdx.y;
    const int sp   = blockIdx.z;
    const int warp = threadIdx.x >> 5;
    const int lane = threadIdx.x & 31;
    const int g = lane >> 2, t = lane & 3;
    const int qb = blockIdx.x * 128 + warp * 32;

    uint4 qh[2], ql[2];
    #pragma unroll
    for (int f = 0; f < 2; f++) {
        const size_t qidx = ((size_t)head * (Ndim / 16) + (qb >> 4) + f) * 32 + lane;
        qh[f] = g_Qh[qidx];
        ql[f] = g_Ql[qidx];
    }

    float o[2][8];
    float lsum[2][2];
    #pragma unroll
    for (int f = 0; f < 2; f++) {
        #pragma unroll
        for (int i = 0; i < 8; i++) o[f][i] = 0.f;
        lsum[f][0] = 0.f; lsum[f][1] = 0.f;
    }

    const int kb0 = sp * (MCHUNK / 16);
    const int nkb = MCHUNK / 16;
    const uint4* Khp = g_Kh + (size_t)head * (Mdim / 16) * 32;
    const uint4* Klp = g_Kl + (size_t)head * (Mdim / 16) * 32;
    const uint4* Vp  = g_Vh + (size_t)head * (Mdim / 16) * 32;

    uint4 kh = Khp[kb0 * 32 + lane];
    uint4 kl = Klp[kb0 * 32 + lane];
    uint4 vv = Vp [kb0 * 32 + lane];

    #pragma unroll 2
    for (int i = 0; i < nkb; i++) {
        const int kb = kb0 + i;
        uint4 kh_n, kl_n, vv_n;
        if (i + 1 < nkb) {
            kh_n = Khp[(kb + 1) * 32 + lane];
            kl_n = Klp[(kb + 1) * 32 + lane];
            vv_n = Vp [(kb + 1) * 32 + lane];
        }

        #pragma unroll
        for (int f = 0; f < 2; f++) {
            float s0, s1, s2, s3;
            mma_f16_z(s0, s1, s2, s3, qh[f].x, qh[f].y, qh[f].z, qh[f].w, kh.x, kh.y);
            mma_f16  (s0, s1, s2, s3, ql[f].x, ql[f].y, ql[f].z, ql[f].w, kh.x, kh.y);
            mma_f16  (s0, s1, s2, s3, qh[f].x, qh[f].y, qh[f].z, qh[f].w, kl.x, kl.y);
            float u0, u1, u2, u3;
            mma_f16_z(u0, u1, u2, u3, qh[f].x, qh[f].y, qh[f].z, qh[f].w, kh.z, kh.w);
            mma_f16  (u0, u1, u2, u3, ql[f].x, ql[f].y, ql[f].z, ql[f].w, kh.z, kh.w);
            mma_f16  (u0, u1, u2, u3, qh[f].x, qh[f].y, qh[f].z, qh[f].w, kl.z, kl.w);

            const uint32_t a0 = pack_h2(ex2f(s0 - SHIFT), ex2f(s1 - SHIFT));
            const uint32_t a1 = pack_h2(ex2f(s2 - SHIFT), ex2f(s3 - SHIFT));
            const uint32_t a2 = pack_h2(ex2f(u0 - SHIFT), ex2f(u1 - SHIFT));
            const uint32_t a3 = pack_h2(ex2f(u2 - SHIFT), ex2f(u3 - SHIFT));

            const float2 f0 = unpack_h2(a0), f1 = unpack_h2(a1);
            const float2 f2 = unpack_h2(a2), f3 = unpack_h2(a3);
            lsum[f][0] += (f0.x + f0.y) + (f2.x + f2.y);
            lsum[f][1] += (f1.x + f1.y) + (f3.x + f3.y);

            mma_f16(o[f][0], o[f][1], o[f][2], o[f][3], a0, a1, a2, a3, vv.x, vv.y);
            mma_f16(o[f][4], o[f][5], o[f][6], o[f][7], a0, a1, a2, a3, vv.z, vv.w);
        }
        kh = kh_n; kl = kl_n; vv = vv_n;
    }

    const size_t pb = ((size_t)head * SPLIT + sp) * Ndim;
    #pragma unroll
    for (int f = 0; f < 2; f++) {
        float l0 = lsum[f][0], l1 = lsum[f][1];
        l0 += __shfl_xor_sync(0xffffffffu, l0, 1);
        l0 += __shfl_xor_sync(0xffffffffu, l0, 2);
        l1 += __shfl_xor_sync(0xffffffffu, l1, 1);
        l1 += __shfl_xor_sync(0xffffffffu, l1, 2);
        const int rlo = qb + 16*f + g;
        const int rhi = rlo + 8;
        if (t == 0) {
            g_Pl[pb + rlo] = l0;
            g_Pl[pb + rhi] = l1;
        }
        #pragma unroll
        for (int c = 0; c < 2; c++) {
            const int d0 = 8 * c + 2 * t;
            *reinterpret_cast<float2*>(g_Po + (pb + rlo) * Ddim + d0) =
                make_float2(o[f][4*c+0], o[f][4*c+1]);
            *reinterpret_cast<float2*>(g_Po + (pb + rhi) * Ddim + d0) =
                make_float2(o[f][4*c+2], o[f][4*c+3]);
        }
    }
}

// ---------------------------------------------------------------------------
// Kernel 2b: combine — one thread per (head, n, d-quad), fully coalesced.
// ---------------------------------------------------------------------------
__global__ __launch_bounds__(128) void combine_kernel(const float* __restrict__ bt)
{
    const int idx  = blockIdx.x * 128 + threadIdx.x;   // 0..131071
    const int head = idx >> 13;
    const int n    = (idx >> 2) & (Ndim - 1);
    const int quad = idx & 3;

    float L = 0.f;
    float4 o = make_float4(0.f, 0.f, 0.f, 0.f);
    #pragma unroll
    for (int s = 0; s < SPLIT; s++) {
        const size_t pb = ((size_t)head * SPLIT + s) * Ndim + n;
        L += g_Pl[pb];
        const float4 v = reinterpret_cast<const float4*>(g_Po)[pb * 4 + quad];
        o.x += v.x; o.y += v.y; o.z += v.z; o.w += v.w;
    }
    const float inv = 1.f / L;

    const int b = head >> 3, k = head & 7;
    const float4 bb = reinterpret_cast<const float4*>(bt)[k * 4 + quad];
    float4 r;
    r.x = o.x * inv + bb.x;
    r.y = o.y * inv + bb.y;
    r.z = o.z * inv + bb.z;
    r.w = o.w * inv + bb.w;
    reinterpret_cast<float4*>(g_O)[(((size_t)(b * Ndim + n)) * Kdim + k) * 4 + quad] = r;
}

// ---------------------------------------------------------------------------
// Kernel 3: output projection as fp16 hi/lo tensor-core GEMM.
// ---------------------------------------------------------------------------
__global__ __launch_bounds__(128) void out_kernel(float* __restrict__ out)
{
    const int row0 = blockIdx.x * 16;
    const int warp = threadIdx.x >> 5;
    const int lane = threadIdx.x & 31;
    const int g = lane >> 2, t = lane & 3;

    float acc[4][4];
    #pragma unroll
    for (int e4 = 0; e4 < 4; e4++)
        #pragma unroll
        for (int i = 0; i < 4; i++) acc[e4][i] = 0.f;

    const float* Orl = g_O + (size_t)(row0 + g    ) * 128;
    const float* Orh = g_O + (size_t)(row0 + g + 8) * 128;

    #pragma unroll
    for (int kc = 0; kc < 8; kc++) {
        const float2 xA = *reinterpret_cast<const float2*>(Orl + kc * 16 + 2 * t);
        const float2 yA = *reinterpret_cast<const float2*>(Orh + kc * 16 + 2 * t);
        const float2 xB = *reinterpret_cast<const float2*>(Orl + kc * 16 + 2 * t + 8);
        const float2 yB = *reinterpret_cast<const float2*>(Orh + kc * 16 + 2 * t + 8);
        const uint32_t ah0 = pack_h2(xA.x, xA.y), al0 = split_lo(xA.x, xA.y, ah0);
        const uint32_t ah1 = pack_h2(yA.x, yA.y), al1 = split_lo(yA.x, yA.y, ah1);
        const uint32_t ah2 = pack_h2(xB.x, xB.y), al2 = split_lo(xB.x, xB.y, ah2);
        const uint32_t ah3 = pack_h2(yB.x, yB.y), al3 = split_lo(yB.x, yB.y, ah3);

        #pragma unroll
        for (int e4 = 0; e4 < 4; e4++) {
            const uint4 wv = g_W[(kc * 16 + (warp * 4 + e4)) * 32 + lane];
            mma_f16(acc[e4][0], acc[e4][1], acc[e4][2], acc[e4][3], ah0, ah1, ah2, ah3, wv.x, wv.y);
            mma_f16(acc[e4][0], acc[e4][1], acc[e4][2], acc[e4][3], al0, al1, al2, al3, wv.x, wv.y);
            mma_f16(acc[e4][0], acc[e4][1], acc[e4][2], acc[e4][3], ah0, ah1, ah2, ah3, wv.z, wv.w);
        }
    }

    #pragma unroll
    for (int e4 = 0; e4 < 4; e4++) {
        const int e0 = (warp * 4 + e4) * 8 + 2 * t;
        *reinterpret_cast<float2*>(out + (size_t)(row0 + g    ) * Edim + e0) =
            make_float2(acc[e4][0], acc[e4][1]);
        *reinterpret_cast<float2*>(out + (size_t)(row0 + g + 8) * Edim + e0) =
            make_float2(acc[e4][2], acc[e4][3]);
    }
}

extern "C" void kernel_launch(void* const* d_in, const int* in_sizes, int n_in,
                              void* d_out, int out_size)
{
    const float* x  = (const float*)d_in[0];
    const float* y  = (const float*)d_in[1];
    const float* l1 = (const float*)d_in[2];
    const float* l2 = (const float*)d_in[3];
    const float* t1 = (const float*)d_in[4];
    const float* t2 = (const float*)d_in[5];
    const float* bl = (const float*)d_in[6];
    const float* bt = (const float*)d_in[7];

    prep_w<<<32, 128>>>(t2);
    prep_proj_w<<<96, 128>>>(l1, t1, l2);
    proj_mma<<<dim3(64, 4, 2), 128>>>(x, y, bl);
    flash_kernel<<<dim3(Ndim / 128, NHEAD, SPLIT), 128>>>();
    combine_kernel<<<NHEAD * Ndim * 4 / 128, 128>>>(bt);
    out_kernel<<<Bdim * Ndim / 16, 128>>>((float*)d_out);
}

// round 10
// speedup vs baseline: 3.3252x; 1.1525x over previous
#include <cuda_runtime.h>
#include <cuda_fp16.h>
#include <math.h>
#include <stdint.h>

// Problem dims (fixed)
#define Bdim 2
#define Mdim 2048
#define Ndim 2048
#define Edim 128
#define Kdim 8
#define Ddim 16
#define NHEAD (Bdim * Kdim)
#define SPLIT 4
#define MCHUNK (Mdim / SPLIT)   // 512 keys per split
#define SHIFT 10.0f             // uniform log2-domain logit shift (softmax-invariant)

// Static scratch (fragment-packed; uint4 = one warp-lane's fragment piece).
__device__ uint4 g_Qh[NHEAD * (size_t)(Ndim / 16) * 32];
__device__ uint4 g_Ql[NHEAD * (size_t)(Ndim / 16) * 32];
__device__ uint4 g_Kh[NHEAD * (size_t)(Mdim / 16) * 32];
__device__ uint4 g_Kl[NHEAD * (size_t)(Mdim / 16) * 32];
__device__ uint4 g_Vh[NHEAD * (size_t)(Mdim / 16) * 32];
__device__ uint4 g_WF[3 * 8 * 8 * 2 * 32];
__device__ uint4 g_W [8 * 16 * 32];
__device__ float g_O [Bdim * (size_t)Ndim * Kdim * Ddim];
__device__ float g_Po[NHEAD * (size_t)SPLIT * Ndim * Ddim];
__device__ float g_Pl[NHEAD * (size_t)SPLIT * Ndim];

__device__ __forceinline__ float ex2f(float x) {
    float r; asm("ex2.approx.f32 %0, %1;" : "=f"(r) : "f"(x)); return r;
}
__device__ __forceinline__ uint32_t pack_h2(float a, float b) {
    __half2 h = __floats2half2_rn(a, b);
    return *reinterpret_cast<uint32_t*>(&h);
}
__device__ __forceinline__ float2 unpack_h2(uint32_t u) {
    __half2 h = *reinterpret_cast<__half2*>(&u);
    return __half22float2(h);
}
__device__ __forceinline__ uint32_t split_lo(float a, float b, uint32_t hi) {
    float2 hf = unpack_h2(hi);
    return pack_h2(a - hf.x, b - hf.y);
}
__device__ __forceinline__ uint32_t movm_t(uint32_t s) {
    uint32_t d;
    asm("movmatrix.sync.aligned.m8n8.trans.b16 %0, %1;" : "=r"(d) : "r"(s));
    return d;
}
__device__ __forceinline__ void mma_f16(float& d0, float& d1, float& d2, float& d3,
                                        uint32_t a0, uint32_t a1, uint32_t a2, uint32_t a3,
                                        uint32_t b0, uint32_t b1) {
    asm volatile("mma.sync.aligned.m16n8k16.row.col.f32.f16.f16.f32 "
                 "{%0,%1,%2,%3},{%4,%5,%6,%7},{%8,%9},{%0,%1,%2,%3};"
                 : "+f"(d0), "+f"(d1), "+f"(d2), "+f"(d3)
                 : "r"(a0), "r"(a1), "r"(a2), "r"(a3), "r"(b0), "r"(b1));
}
// D = A*B + {c,c,c,c} — starts a chain with a scalar C-init (used to fold -SHIFT)
__device__ __forceinline__ void mma_f16_c(float& d0, float& d1, float& d2, float& d3,
                                          uint32_t a0, uint32_t a1, uint32_t a2, uint32_t a3,
                                          uint32_t b0, uint32_t b1, float c) {
    asm volatile("mma.sync.aligned.m16n8k16.row.col.f32.f16.f16.f32 "
                 "{%0,%1,%2,%3},{%4,%5,%6,%7},{%8,%9},{%10,%10,%10,%10};"
                 : "=f"(d0), "=f"(d1), "=f"(d2), "=f"(d3)
                 : "r"(a0), "r"(a1), "r"(a2), "r"(a3), "r"(b0), "r"(b1), "f"(c));
}

// ---------------------------------------------------------------------------
// Kernel 0a: pack theta2 into fp16 hi/lo B-fragments (output GEMM).
// ---------------------------------------------------------------------------
__global__ __launch_bounds__(128) void prep_w(const float* __restrict__ t2)
{
    const int idx  = blockIdx.x * 128 + threadIdx.x;
    const int kc   = idx >> 9;
    const int et   = (idx >> 5) & 15;
    const int lane = idx & 31;
    const int g = lane >> 2, t = lane & 3;
    const int e = et * 8 + g;

    const float2 wA = *reinterpret_cast<const float2*>(t2 + ((size_t)kc * Edim + e) * Ddim + 2 * t);
    const float2 wB = *reinterpret_cast<const float2*>(t2 + ((size_t)kc * Edim + e) * Ddim + 2 * t + 8);
    const uint32_t h0 = pack_h2(wA.x, wA.y), l0 = split_lo(wA.x, wA.y, h0);
    const uint32_t h1 = pack_h2(wB.x, wB.y), l1 = split_lo(wB.x, wB.y, h1);
    g_W[(kc * 16 + et) * 32 + lane] = make_uint4(h0, h1, l0, l1);
}

// ---------------------------------------------------------------------------
// Kernel 0b: pack proj weights (l1, t1, l2*sc) into hi/lo B-fragments.
// ---------------------------------------------------------------------------
__global__ __launch_bounds__(128) void prep_proj_w(
    const float* __restrict__ l1, const float* __restrict__ t1, const float* __restrict__ l2)
{
    const int idx  = blockIdx.x * 128 + threadIdx.x;
    const int lane = idx & 31;
    const int nt   = (idx >> 5) & 1;
    const int c    = (idx >> 6) & 7;
    const int k    = (idx >> 9) & 7;
    const int a    = idx >> 12;
    const int g = lane >> 2, t = lane & 3;

    const float* W = (a == 0) ? l1 : (a == 1) ? t1 : l2;
    const float s  = (a == 2) ? (0.25f * 1.4426950408889634f) : 1.0f;
    const int d  = nt * 8 + g;
    const int e0 = c * 16 + 2 * t;

    const float w00 = W[((size_t)k * Edim + e0    ) * Ddim + d] * s;
    const float w01 = W[((size_t)k * Edim + e0 + 1) * Ddim + d] * s;
    const float w10 = W[((size_t)k * Edim + e0 + 8) * Ddim + d] * s;
    const float w11 = W[((size_t)k * Edim + e0 + 9) * Ddim + d] * s;
    const uint32_t h0 = pack_h2(w00, w01), lo0 = split_lo(w00, w01, h0);
    const uint32_t h1 = pack_h2(w10, w11), lo1 = split_lo(w10, w11, h1);
    g_WF[((a * 8 + k) * 8 + c) * 64 + nt * 32 + lane] = make_uint4(h0, h1, lo0, lo1);
}

// ---------------------------------------------------------------------------
// Kernel 1: projections as fp16 hi/lo MMA (3-pass Dekker), register-exact
// packing into the flash fragment layouts (K/Q: pair-pack; V: movmatrix).
// ---------------------------------------------------------------------------
__global__ __launch_bounds__(128) void proj_mma(
    const float* __restrict__ x, const float* __restrict__ y,
    const float* __restrict__ bl)
{
    const int warp = threadIdx.x >> 5;
    const int lane = threadIdx.x & 31;
    const int g = lane >> 2, t = lane & 3;
    const int tile = blockIdx.x * 4 + warp;
    const int hp   = blockIdx.y;
    const bool isQ = (blockIdx.z != 0);
    const int row0 = tile * 16;
    const int b    = row0 >> 11;
    const int m0   = row0 & (Mdim - 1);

    const float* src = isQ ? y : x;
    uint32_t ahi[8][4], alo[8][4];
    #pragma unroll
    for (int c = 0; c < 8; c++) {
        const float* base = src + (size_t)row0 * Edim + c * 16;
        const float2 v0 = *reinterpret_cast<const float2*>(base + (g    ) * Edim + 2 * t);
        const float2 v1 = *reinterpret_cast<const float2*>(base + (g + 8) * Edim + 2 * t);
        const float2 v2 = *reinterpret_cast<const float2*>(base + (g    ) * Edim + 2 * t + 8);
        const float2 v3 = *reinterpret_cast<const float2*>(base + (g + 8) * Edim + 2 * t + 8);
        ahi[c][0] = pack_h2(v0.x, v0.y); alo[c][0] = split_lo(v0.x, v0.y, ahi[c][0]);
        ahi[c][1] = pack_h2(v1.x, v1.y); alo[c][1] = split_lo(v1.x, v1.y, ahi[c][1]);
        ahi[c][2] = pack_h2(v2.x, v2.y); alo[c][2] = split_lo(v2.x, v2.y, ahi[c][2]);
        ahi[c][3] = pack_h2(v3.x, v3.y); alo[c][3] = split_lo(v3.x, v3.y, ahi[c][3]);
    }

    #pragma unroll
    for (int hh = 0; hh < 2; hh++) {
        const int k = hp * 2 + hh;
        const int head = b * Kdim + k;
        const size_t oidx = ((size_t)head * (Mdim / 16) + (m0 >> 4)) * 32 + lane;

        if (!isQ) {
            float cK[2][4], cV[2][4];
            #pragma unroll
            for (int nt = 0; nt < 2; nt++)
                #pragma unroll
                for (int i = 0; i < 4; i++) { cK[nt][i] = 0.f; cV[nt][i] = 0.f; }

            #pragma unroll
            for (int c = 0; c < 8; c++) {
                #pragma unroll
                for (int nt = 0; nt < 2; nt++) {
                    const uint4 wK = g_WF[((0 * 8 + k) * 8 + c) * 64 + nt * 32 + lane];
                    mma_f16(cK[nt][0], cK[nt][1], cK[nt][2], cK[nt][3],
                            ahi[c][0], ahi[c][1], ahi[c][2], ahi[c][3], wK.x, wK.y);
                    mma_f16(cK[nt][0], cK[nt][1], cK[nt][2], cK[nt][3],
                            alo[c][0], alo[c][1], alo[c][2], alo[c][3], wK.x, wK.y);
                    mma_f16(cK[nt][0], cK[nt][1], cK[nt][2], cK[nt][3],
                            ahi[c][0], ahi[c][1], ahi[c][2], ahi[c][3], wK.z, wK.w);
                    const uint4 wV = g_WF[((1 * 8 + k) * 8 + c) * 64 + nt * 32 + lane];
                    mma_f16(cV[nt][0], cV[nt][1], cV[nt][2], cV[nt][3],
                            ahi[c][0], ahi[c][1], ahi[c][2], ahi[c][3], wV.x, wV.y);
                    mma_f16(cV[nt][0], cV[nt][1], cV[nt][2], cV[nt][3],
                            alo[c][0], alo[c][1], alo[c][2], alo[c][3], wV.x, wV.y);
                    mma_f16(cV[nt][0], cV[nt][1], cV[nt][2], cV[nt][3],
                            ahi[c][0], ahi[c][1], ahi[c][2], ahi[c][3], wV.z, wV.w);
                }
            }

            const float2 bl0 = *reinterpret_cast<const float2*>(bl + k * Ddim + 2 * t);
            const float2 bl1 = *reinterpret_cast<const float2*>(bl + k * Ddim + 8 + 2 * t);
            cK[0][0] += bl0.x; cK[0][1] += bl0.y; cK[0][2] += bl0.x; cK[0][3] += bl0.y;
            cK[1][0] += bl1.x; cK[1][1] += bl1.y; cK[1][2] += bl1.x; cK[1][3] += bl1.y;

            uint4 kh, kl;
            kh.x = pack_h2(cK[0][0], cK[0][1]); kl.x = split_lo(cK[0][0], cK[0][1], kh.x);
            kh.y = pack_h2(cK[1][0], cK[1][1]); kl.y = split_lo(cK[1][0], cK[1][1], kh.y);
            kh.z = pack_h2(cK[0][2], cK[0][3]); kl.z = split_lo(cK[0][2], cK[0][3], kh.z);
            kh.w = pack_h2(cK[1][2], cK[1][3]); kl.w = split_lo(cK[1][2], cK[1][3], kh.w);
            g_Kh[oidx] = kh;
            g_Kl[oidx] = kl;

            uint4 vv;
            vv.x = movm_t(pack_h2(cV[0][0], cV[0][1]));
            vv.y = movm_t(pack_h2(cV[0][2], cV[0][3]));
            vv.z = movm_t(pack_h2(cV[1][0], cV[1][1]));
            vv.w = movm_t(pack_h2(cV[1][2], cV[1][3]));
            g_Vh[oidx] = vv;
        } else {
            float cQ[2][4];
            #pragma unroll
            for (int nt = 0; nt < 2; nt++)
                #pragma unroll
                for (int i = 0; i < 4; i++) cQ[nt][i] = 0.f;

            #pragma unroll
            for (int c = 0; c < 8; c++) {
                #pragma unroll
                for (int nt = 0; nt < 2; nt++) {
                    const uint4 wQ = g_WF[((2 * 8 + k) * 8 + c) * 64 + nt * 32 + lane];
                    mma_f16(cQ[nt][0], cQ[nt][1], cQ[nt][2], cQ[nt][3],
                            ahi[c][0], ahi[c][1], ahi[c][2], ahi[c][3], wQ.x, wQ.y);
                    mma_f16(cQ[nt][0], cQ[nt][1], cQ[nt][2], cQ[nt][3],
                            alo[c][0], alo[c][1], alo[c][2], alo[c][3], wQ.x, wQ.y);
                    mma_f16(cQ[nt][0], cQ[nt][1], cQ[nt][2], cQ[nt][3],
                            ahi[c][0], ahi[c][1], ahi[c][2], ahi[c][3], wQ.z, wQ.w);
                }
            }
            uint4 qh, ql;
            qh.x = pack_h2(cQ[0][0], cQ[0][1]); ql.x = split_lo(cQ[0][0], cQ[0][1], qh.x);
            qh.y = pack_h2(cQ[0][2], cQ[0][3]); ql.y = split_lo(cQ[0][2], cQ[0][3], qh.y);
            qh.z = pack_h2(cQ[1][0], cQ[1][1]); ql.z = split_lo(cQ[1][0], cQ[1][1], qh.z);
            qh.w = pack_h2(cQ[1][2], cQ[1][3]); ql.w = split_lo(cQ[1][2], cQ[1][3], qh.w);
            g_Qh[oidx] = qh;
            g_Ql[oidx] = ql;
        }
    }
}

// ---------------------------------------------------------------------------
// Kernel 2: flash attention via fp16 hi/lo mma.m16n8k16, split-K (4 splits).
// -SHIFT folded into QK^T C-init; l computed by a ones-column MMA on the
// SAME fp16 P fragments (bit-identical weights, zero cvt/add bookkeeping).
// ---------------------------------------------------------------------------
__global__ __launch_bounds__(128) void flash_kernel()
{
    const int head = blockIdx.y;
    const int sp   = blockIdx.z;
    const int warp = threadIdx.x >> 5;
    const int lane = threadIdx.x & 31;
    const int g = lane >> 2, t = lane & 3;
    const int qb = blockIdx.x * 128 + warp * 32;

    uint4 qh[2], ql[2];
    #pragma unroll
    for (int f = 0; f < 2; f++) {
        const size_t qidx = ((size_t)head * (Ndim / 16) + (qb >> 4) + f) * 32 + lane;
        qh[f] = g_Qh[qidx];
        ql[f] = g_Ql[qidx];
    }

    // ones-in-column-0 B fragment: lanes 0-3 hold {1,1}h2 in b0 and b1
    const uint32_t ones = (g == 0) ? 0x3C003C00u : 0u;

    float o[2][8];
    float lac[2][4];
    #pragma unroll
    for (int f = 0; f < 2; f++) {
        #pragma unroll
        for (int i = 0; i < 8; i++) o[f][i] = 0.f;
        #pragma unroll
        for (int i = 0; i < 4; i++) lac[f][i] = 0.f;
    }

    const int kb0 = sp * (MCHUNK / 16);
    const int nkb = MCHUNK / 16;
    const int kbLast = kb0 + nkb - 1;
    const uint4* Khp = g_Kh + (size_t)head * (Mdim / 16) * 32;
    const uint4* Klp = g_Kl + (size_t)head * (Mdim / 16) * 32;
    const uint4* Vp  = g_Vh + (size_t)head * (Mdim / 16) * 32;

    uint4 kh = Khp[kb0 * 32 + lane];
    uint4 kl = Klp[kb0 * 32 + lane];
    uint4 vv = Vp [kb0 * 32 + lane];

    #pragma unroll 4
    for (int i = 0; i < nkb; i++) {
        // branch-free prefetch (clamped index; redundant last load stays in-bounds)
        const int kbn = (kb0 + i + 1 <= kbLast) ? (kb0 + i + 1) : kbLast;
        const uint4 kh_n = Khp[kbn * 32 + lane];
        const uint4 kl_n = Klp[kbn * 32 + lane];
        const uint4 vv_n = Vp [kbn * 32 + lane];

        #pragma unroll
        for (int f = 0; f < 2; f++) {
            float s0, s1, s2, s3;
            mma_f16_c(s0, s1, s2, s3, qh[f].x, qh[f].y, qh[f].z, qh[f].w, kh.x, kh.y, -SHIFT);
            mma_f16  (s0, s1, s2, s3, ql[f].x, ql[f].y, ql[f].z, ql[f].w, kh.x, kh.y);
            mma_f16  (s0, s1, s2, s3, qh[f].x, qh[f].y, qh[f].z, qh[f].w, kl.x, kl.y);
            float u0, u1, u2, u3;
            mma_f16_c(u0, u1, u2, u3, qh[f].x, qh[f].y, qh[f].z, qh[f].w, kh.z, kh.w, -SHIFT);
            mma_f16  (u0, u1, u2, u3, ql[f].x, ql[f].y, ql[f].z, ql[f].w, kh.z, kh.w);
            mma_f16  (u0, u1, u2, u3, qh[f].x, qh[f].y, qh[f].z, qh[f].w, kl.z, kl.w);

            const uint32_t a0 = pack_h2(ex2f(s0), ex2f(s1));
            const uint32_t a1 = pack_h2(ex2f(s2), ex2f(s3));
            const uint32_t a2 = pack_h2(ex2f(u0), ex2f(u1));
            const uint32_t a3 = pack_h2(ex2f(u2), ex2f(u3));

            // l accumulation on the tensor pipe: D[r][0] += sum_k P[r][k]
            mma_f16(lac[f][0], lac[f][1], lac[f][2], lac[f][3], a0, a1, a2, a3, ones, ones);

            mma_f16(o[f][0], o[f][1], o[f][2], o[f][3], a0, a1, a2, a3, vv.x, vv.y);
            mma_f16(o[f][4], o[f][5], o[f][6], o[f][7], a0, a1, a2, a3, vv.z, vv.w);
        }
        kh = kh_n; kl = kl_n; vv = vv_n;
    }

    const size_t pb = ((size_t)head * SPLIT + sp) * Ndim;
    #pragma unroll
    for (int f = 0; f < 2; f++) {
        const int rlo = qb + 16*f + g;
        const int rhi = rlo + 8;
        if (t == 0) {                       // col 0 of the ones-MMA = full row sum
            g_Pl[pb + rlo] = lac[f][0];
            g_Pl[pb + rhi] = lac[f][2];
        }
        #pragma unroll
        for (int c = 0; c < 2; c++) {
            const int d0 = 8 * c + 2 * t;
            *reinterpret_cast<float2*>(g_Po + (pb + rlo) * Ddim + d0) =
                make_float2(o[f][4*c+0], o[f][4*c+1]);
            *reinterpret_cast<float2*>(g_Po + (pb + rhi) * Ddim + d0) =
                make_float2(o[f][4*c+2], o[f][4*c+3]);
        }
    }
}

// ---------------------------------------------------------------------------
// Kernel 2b: combine — one thread per (head, n, d-quad), fully coalesced.
// ---------------------------------------------------------------------------
__global__ __launch_bounds__(128) void combine_kernel(const float* __restrict__ bt)
{
    const int idx  = blockIdx.x * 128 + threadIdx.x;
    const int head = idx >> 13;
    const int n    = (idx >> 2) & (Ndim - 1);
    const int quad = idx & 3;

    float L = 0.f;
    float4 o = make_float4(0.f, 0.f, 0.f, 0.f);
    #pragma unroll
    for (int s = 0; s < SPLIT; s++) {
        const size_t pb = ((size_t)head * SPLIT + s) * Ndim + n;
        L += g_Pl[pb];
        const float4 v = reinterpret_cast<const float4*>(g_Po)[pb * 4 + quad];
        o.x += v.x; o.y += v.y; o.z += v.z; o.w += v.w;
    }
    const float inv = 1.f / L;

    const int b = head >> 3, k = head & 7;
    const float4 bb = reinterpret_cast<const float4*>(bt)[k * 4 + quad];
    float4 r;
    r.x = o.x * inv + bb.x;
    r.y = o.y * inv + bb.y;
    r.z = o.z * inv + bb.z;
    r.w = o.w * inv + bb.w;
    reinterpret_cast<float4*>(g_O)[(((size_t)(b * Ndim + n)) * Kdim + k) * 4 + quad] = r;
}

// ---------------------------------------------------------------------------
// Kernel 3: output projection as fp16 hi/lo tensor-core GEMM.
// ---------------------------------------------------------------------------
__global__ __launch_bounds__(128) void out_kernel(float* __restrict__ out)
{
    const int row0 = blockIdx.x * 16;
    const int warp = threadIdx.x >> 5;
    const int lane = threadIdx.x & 31;
    const int g = lane >> 2, t = lane & 3;

    float acc[4][4];
    #pragma unroll
    for (int e4 = 0; e4 < 4; e4++)
        #pragma unroll
        for (int i = 0; i < 4; i++) acc[e4][i] = 0.f;

    const float* Orl = g_O + (size_t)(row0 + g    ) * 128;
    const float* Orh = g_O + (size_t)(row0 + g + 8) * 128;

    #pragma unroll
    for (int kc = 0; kc < 8; kc++) {
        const float2 xA = *reinterpret_cast<const float2*>(Orl + kc * 16 + 2 * t);
        const float2 yA = *reinterpret_cast<const float2*>(Orh + kc * 16 + 2 * t);
        const float2 xB = *reinterpret_cast<const float2*>(Orl + kc * 16 + 2 * t + 8);
        const float2 yB = *reinterpret_cast<const float2*>(Orh + kc * 16 + 2 * t + 8);
        const uint32_t ah0 = pack_h2(xA.x, xA.y), al0 = split_lo(xA.x, xA.y, ah0);
        const uint32_t ah1 = pack_h2(yA.x, yA.y), al1 = split_lo(yA.x, yA.y, ah1);
        const uint32_t ah2 = pack_h2(xB.x, xB.y), al2 = split_lo(xB.x, xB.y, ah2);
        const uint32_t ah3 = pack_h2(yB.x, yB.y), al3 = split_lo(yB.x, yB.y, ah3);

        #pragma unroll
        for (int e4 = 0; e4 < 4; e4++) {
            const uint4 wv = g_W[(kc * 16 + (warp * 4 + e4)) * 32 + lane];
            mma_f16(acc[e4][0], acc[e4][1], acc[e4][2], acc[e4][3], ah0, ah1, ah2, ah3, wv.x, wv.y);
            mma_f16(acc[e4][0], acc[e4][1], acc[e4][2], acc[e4][3], al0, al1, al2, al3, wv.x, wv.y);
            mma_f16(acc[e4][0], acc[e4][1], acc[e4][2], acc[e4][3], ah0, ah1, ah2, ah3, wv.z, wv.w);
        }
    }

    #pragma unroll
    for (int e4 = 0; e4 < 4; e4++) {
        const int e0 = (warp * 4 + e4) * 8 + 2 * t;
        *reinterpret_cast<float2*>(out + (size_t)(row0 + g    ) * Edim + e0) =
            make_float2(acc[e4][0], acc[e4][1]);
        *reinterpret_cast<float2*>(out + (size_t)(row0 + g + 8) * Edim + e0) =
            make_float2(acc[e4][2], acc[e4][3]);
    }
}

extern "C" void kernel_launch(void* const* d_in, const int* in_sizes, int n_in,
                              void* d_out, int out_size)
{
    const float* x  = (const float*)d_in[0];
    const float* y  = (const float*)d_in[1];
    const float* l1 = (const float*)d_in[2];
    const float* l2 = (const float*)d_in[3];
    const float* t1 = (const float*)d_in[4];
    const float* t2 = (const float*)d_in[5];
    const float* bl = (const float*)d_in[6];
    const float* bt = (const float*)d_in[7];

    prep_w<<<32, 128>>>(t2);
    prep_proj_w<<<96, 128>>>(l1, t1, l2);
    proj_mma<<<dim3(64, 4, 2), 128>>>(x, y, bl);
    flash_kernel<<<dim3(Ndim / 128, NHEAD, SPLIT), 128>>>();
    combine_kernel<<<NHEAD * Ndim * 4 / 128, 128>>>(bt);
    out_kernel<<<Bdim * Ndim / 16, 128>>>((float*)d_out);
}

// round 11
// speedup vs baseline: 3.5973x; 1.0818x over previous
#include <cuda_runtime.h>
#include <cuda_fp16.h>
#include <math.h>
#include <stdint.h>

// Problem dims (fixed)
#define Bdim 2
#define Mdim 2048
#define Ndim 2048
#define Edim 128
#define Kdim 8
#define Ddim 16
#define NHEAD (Bdim * Kdim)
#define SPLIT 4
#define MCHUNK (Mdim / SPLIT)   // 512 keys per split
#define SHIFT 10.0f             // uniform log2-domain logit shift (softmax-invariant)

// Static scratch (fragment-packed; uint4 = one warp-lane's fragment piece).
__device__ uint4 g_Qh[NHEAD * (size_t)(Ndim / 16) * 32];
__device__ uint4 g_Ql[NHEAD * (size_t)(Ndim / 16) * 32];
__device__ uint4 g_Kh[NHEAD * (size_t)(Mdim / 16) * 32];
__device__ uint4 g_Kl[NHEAD * (size_t)(Mdim / 16) * 32];
__device__ uint4 g_Vh[NHEAD * (size_t)(Mdim / 16) * 32];
__device__ uint4 g_WF[3 * 8 * 8 * 2 * 32];
__device__ uint4 g_W [8 * 16 * 32];
__device__ float g_O [Bdim * (size_t)Ndim * Kdim * Ddim];
__device__ float g_Po[NHEAD * (size_t)SPLIT * Ndim * Ddim];
__device__ float g_Pl[NHEAD * (size_t)SPLIT * Ndim];

__device__ __forceinline__ float ex2f(float x) {
    float r; asm("ex2.approx.f32 %0, %1;" : "=f"(r) : "f"(x)); return r;
}
__device__ __forceinline__ uint32_t pack_h2(float a, float b) {
    __half2 h = __floats2half2_rn(a, b);
    return *reinterpret_cast<uint32_t*>(&h);
}
__device__ __forceinline__ float2 unpack_h2(uint32_t u) {
    __half2 h = *reinterpret_cast<__half2*>(&u);
    return __half22float2(h);
}
__device__ __forceinline__ uint32_t split_lo(float a, float b, uint32_t hi) {
    float2 hf = unpack_h2(hi);
    return pack_h2(a - hf.x, b - hf.y);
}
__device__ __forceinline__ uint32_t movm_t(uint32_t s) {
    uint32_t d;
    asm("movmatrix.sync.aligned.m8n8.trans.b16 %0, %1;" : "=r"(d) : "r"(s));
    return d;
}
__device__ __forceinline__ void cp_async16(uint32_t saddr, const void* g) {
    asm volatile("cp.async.cg.shared.global [%0], [%1], 16;" :: "r"(saddr), "l"(g));
}
#define CP_COMMIT() asm volatile("cp.async.commit_group;" ::: "memory")
#define CP_WAIT1()  asm volatile("cp.async.wait_group 1;" ::: "memory")

__device__ __forceinline__ void mma_f16(float& d0, float& d1, float& d2, float& d3,
                                        uint32_t a0, uint32_t a1, uint32_t a2, uint32_t a3,
                                        uint32_t b0, uint32_t b1) {
    asm volatile("mma.sync.aligned.m16n8k16.row.col.f32.f16.f16.f32 "
                 "{%0,%1,%2,%3},{%4,%5,%6,%7},{%8,%9},{%0,%1,%2,%3};"
                 : "+f"(d0), "+f"(d1), "+f"(d2), "+f"(d3)
                 : "r"(a0), "r"(a1), "r"(a2), "r"(a3), "r"(b0), "r"(b1));
}
__device__ __forceinline__ void mma_f16_c(float& d0, float& d1, float& d2, float& d3,
                                          uint32_t a0, uint32_t a1, uint32_t a2, uint32_t a3,
                                          uint32_t b0, uint32_t b1, float c) {
    asm volatile("mma.sync.aligned.m16n8k16.row.col.f32.f16.f16.f32 "
                 "{%0,%1,%2,%3},{%4,%5,%6,%7},{%8,%9},{%10,%10,%10,%10};"
                 : "=f"(d0), "=f"(d1), "=f"(d2), "=f"(d3)
                 : "r"(a0), "r"(a1), "r"(a2), "r"(a3), "r"(b0), "r"(b1), "f"(c));
}

// ---------------------------------------------------------------------------
// Kernel 0a: pack theta2 into fp16 hi/lo B-fragments (output GEMM).
// ---------------------------------------------------------------------------
__global__ __launch_bounds__(128) void prep_w(const float* __restrict__ t2)
{
    const int idx  = blockIdx.x * 128 + threadIdx.x;
    const int kc   = idx >> 9;
    const int et   = (idx >> 5) & 15;
    const int lane = idx & 31;
    const int g = lane >> 2, t = lane & 3;
    const int e = et * 8 + g;

    const float2 wA = *reinterpret_cast<const float2*>(t2 + ((size_t)kc * Edim + e) * Ddim + 2 * t);
    const float2 wB = *reinterpret_cast<const float2*>(t2 + ((size_t)kc * Edim + e) * Ddim + 2 * t + 8);
    const uint32_t h0 = pack_h2(wA.x, wA.y), l0 = split_lo(wA.x, wA.y, h0);
    const uint32_t h1 = pack_h2(wB.x, wB.y), l1 = split_lo(wB.x, wB.y, h1);
    g_W[(kc * 16 + et) * 32 + lane] = make_uint4(h0, h1, l0, l1);
}

// ---------------------------------------------------------------------------
// Kernel 0b: pack proj weights (l1, t1, l2*sc) into hi/lo B-fragments.
// ---------------------------------------------------------------------------
__global__ __launch_bounds__(128) void prep_proj_w(
    const float* __restrict__ l1, const float* __restrict__ t1, const float* __restrict__ l2)
{
    const int idx  = blockIdx.x * 128 + threadIdx.x;
    const int lane = idx & 31;
    const int nt   = (idx >> 5) & 1;
    const int c    = (idx >> 6) & 7;
    const int k    = (idx >> 9) & 7;
    const int a    = idx >> 12;
    const int g = lane >> 2, t = lane & 3;

    const float* W = (a == 0) ? l1 : (a == 1) ? t1 : l2;
    const float s  = (a == 2) ? (0.25f * 1.4426950408889634f) : 1.0f;
    const int d  = nt * 8 + g;
    const int e0 = c * 16 + 2 * t;

    const float w00 = W[((size_t)k * Edim + e0    ) * Ddim + d] * s;
    const float w01 = W[((size_t)k * Edim + e0 + 1) * Ddim + d] * s;
    const float w10 = W[((size_t)k * Edim + e0 + 8) * Ddim + d] * s;
    const float w11 = W[((size_t)k * Edim + e0 + 9) * Ddim + d] * s;
    const uint32_t h0 = pack_h2(w00, w01), lo0 = split_lo(w00, w01, h0);
    const uint32_t h1 = pack_h2(w10, w11), lo1 = split_lo(w10, w11, h1);
    g_WF[((a * 8 + k) * 8 + c) * 64 + nt * 32 + lane] = make_uint4(h0, h1, lo0, lo1);
}

// ---------------------------------------------------------------------------
// Kernel 1: projections as fp16 hi/lo MMA (3-pass Dekker), register-exact
// packing into the flash fragment layouts (K/Q: pair-pack; V: movmatrix).
// ---------------------------------------------------------------------------
__global__ __launch_bounds__(128) void proj_mma(
    const float* __restrict__ x, const float* __restrict__ y,
    const float* __restrict__ bl)
{
    const int warp = threadIdx.x >> 5;
    const int lane = threadIdx.x & 31;
    const int g = lane >> 2, t = lane & 3;
    const int tile = blockIdx.x * 4 + warp;
    const int hp   = blockIdx.y;
    const bool isQ = (blockIdx.z != 0);
    const int row0 = tile * 16;
    const int b    = row0 >> 11;
    const int m0   = row0 & (Mdim - 1);

    const float* src = isQ ? y : x;
    uint32_t ahi[8][4], alo[8][4];
    #pragma unroll
    for (int c = 0; c < 8; c++) {
        const float* base = src + (size_t)row0 * Edim + c * 16;
        const float2 v0 = *reinterpret_cast<const float2*>(base + (g    ) * Edim + 2 * t);
        const float2 v1 = *reinterpret_cast<const float2*>(base + (g + 8) * Edim + 2 * t);
        const float2 v2 = *reinterpret_cast<const float2*>(base + (g    ) * Edim + 2 * t + 8);
        const float2 v3 = *reinterpret_cast<const float2*>(base + (g + 8) * Edim + 2 * t + 8);
        ahi[c][0] = pack_h2(v0.x, v0.y); alo[c][0] = split_lo(v0.x, v0.y, ahi[c][0]);
        ahi[c][1] = pack_h2(v1.x, v1.y); alo[c][1] = split_lo(v1.x, v1.y, ahi[c][1]);
        ahi[c][2] = pack_h2(v2.x, v2.y); alo[c][2] = split_lo(v2.x, v2.y, ahi[c][2]);
        ahi[c][3] = pack_h2(v3.x, v3.y); alo[c][3] = split_lo(v3.x, v3.y, ahi[c][3]);
    }

    #pragma unroll
    for (int hh = 0; hh < 2; hh++) {
        const int k = hp * 2 + hh;
        const int head = b * Kdim + k;
        const size_t oidx = ((size_t)head * (Mdim / 16) + (m0 >> 4)) * 32 + lane;

        if (!isQ) {
            float cK[2][4], cV[2][4];
            #pragma unroll
            for (int nt = 0; nt < 2; nt++)
                #pragma unroll
                for (int i = 0; i < 4; i++) { cK[nt][i] = 0.f; cV[nt][i] = 0.f; }

            #pragma unroll
            for (int c = 0; c < 8; c++) {
                #pragma unroll
                for (int nt = 0; nt < 2; nt++) {
                    const uint4 wK = g_WF[((0 * 8 + k) * 8 + c) * 64 + nt * 32 + lane];
                    mma_f16(cK[nt][0], cK[nt][1], cK[nt][2], cK[nt][3],
                            ahi[c][0], ahi[c][1], ahi[c][2], ahi[c][3], wK.x, wK.y);
                    mma_f16(cK[nt][0], cK[nt][1], cK[nt][2], cK[nt][3],
                            alo[c][0], alo[c][1], alo[c][2], alo[c][3], wK.x, wK.y);
                    mma_f16(cK[nt][0], cK[nt][1], cK[nt][2], cK[nt][3],
                            ahi[c][0], ahi[c][1], ahi[c][2], ahi[c][3], wK.z, wK.w);
                    const uint4 wV = g_WF[((1 * 8 + k) * 8 + c) * 64 + nt * 32 + lane];
                    mma_f16(cV[nt][0], cV[nt][1], cV[nt][2], cV[nt][3],
                            ahi[c][0], ahi[c][1], ahi[c][2], ahi[c][3], wV.x, wV.y);
                    mma_f16(cV[nt][0], cV[nt][1], cV[nt][2], cV[nt][3],
                            alo[c][0], alo[c][1], alo[c][2], alo[c][3], wV.x, wV.y);
                    mma_f16(cV[nt][0], cV[nt][1], cV[nt][2], cV[nt][3],
                            ahi[c][0], ahi[c][1], ahi[c][2], ahi[c][3], wV.z, wV.w);
                }
            }

            const float2 bl0 = *reinterpret_cast<const float2*>(bl + k * Ddim + 2 * t);
            const float2 bl1 = *reinterpret_cast<const float2*>(bl + k * Ddim + 8 + 2 * t);
            cK[0][0] += bl0.x; cK[0][1] += bl0.y; cK[0][2] += bl0.x; cK[0][3] += bl0.y;
            cK[1][0] += bl1.x; cK[1][1] += bl1.y; cK[1][2] += bl1.x; cK[1][3] += bl1.y;

            uint4 kh, kl;
            kh.x = pack_h2(cK[0][0], cK[0][1]); kl.x = split_lo(cK[0][0], cK[0][1], kh.x);
            kh.y = pack_h2(cK[1][0], cK[1][1]); kl.y = split_lo(cK[1][0], cK[1][1], kh.y);
            kh.z = pack_h2(cK[0][2], cK[0][3]); kl.z = split_lo(cK[0][2], cK[0][3], kh.z);
            kh.w = pack_h2(cK[1][2], cK[1][3]); kl.w = split_lo(cK[1][2], cK[1][3], kh.w);
            g_Kh[oidx] = kh;
            g_Kl[oidx] = kl;

            uint4 vv;
            vv.x = movm_t(pack_h2(cV[0][0], cV[0][1]));
            vv.y = movm_t(pack_h2(cV[0][2], cV[0][3]));
            vv.z = movm_t(pack_h2(cV[1][0], cV[1][1]));
            vv.w = movm_t(pack_h2(cV[1][2], cV[1][3]));
            g_Vh[oidx] = vv;
        } else {
            float cQ[2][4];
            #pragma unroll
            for (int nt = 0; nt < 2; nt++)
                #pragma unroll
                for (int i = 0; i < 4; i++) cQ[nt][i] = 0.f;

            #pragma unroll
            for (int c = 0; c < 8; c++) {
                #pragma unroll
                for (int nt = 0; nt < 2; nt++) {
                    const uint4 wQ = g_WF[((2 * 8 + k) * 8 + c) * 64 + nt * 32 + lane];
                    mma_f16(cQ[nt][0], cQ[nt][1], cQ[nt][2], cQ[nt][3],
                            ahi[c][0], ahi[c][1], ahi[c][2], ahi[c][3], wQ.x, wQ.y);
                    mma_f16(cQ[nt][0], cQ[nt][1], cQ[nt][2], cQ[nt][3],
                            alo[c][0], alo[c][1], alo[c][2], alo[c][3], wQ.x, wQ.y);
                    mma_f16(cQ[nt][0], cQ[nt][1], cQ[nt][2], cQ[nt][3],
                            ahi[c][0], ahi[c][1], ahi[c][2], ahi[c][3], wQ.z, wQ.w);
                }
            }
            uint4 qh, ql;
            qh.x = pack_h2(cQ[0][0], cQ[0][1]); ql.x = split_lo(cQ[0][0], cQ[0][1], qh.x);
            qh.y = pack_h2(cQ[0][2], cQ[0][3]); ql.y = split_lo(cQ[0][2], cQ[0][3], qh.y);
            qh.z = pack_h2(cQ[1][0], cQ[1][1]); ql.z = split_lo(cQ[1][0], cQ[1][1], qh.z);
            qh.w = pack_h2(cQ[1][2], cQ[1][3]); ql.w = split_lo(cQ[1][2], cQ[1][3], qh.w);
            g_Qh[oidx] = qh;
            g_Ql[oidx] = ql;
        }
    }
}

// ---------------------------------------------------------------------------
// Kernel 2: flash attention, fp16 hi/lo mma, split-K, cp.async smem pipeline.
// 3-stage double... triple buffer; warps 0/1/2 each stream one array
// (Kh/Kl/V) into smem; all warps consume via conflict-free LDS.128.
// One __syncthreads per key tile. -SHIFT folded into C-init; l via ones-MMA.
// ---------------------------------------------------------------------------
__global__ __launch_bounds__(128) void flash_kernel()
{
    __shared__ __align__(16) uint4 sbuf[3][96];   // [stage][arr*32 + lane]

    const int head = blockIdx.y;
    const int sp   = blockIdx.z;
    const int tid  = threadIdx.x;
    const int warp = tid >> 5;
    const int lane = tid & 31;
    const int g = lane >> 2, t = lane & 3;
    const int qb = blockIdx.x * 128 + warp * 32;

    uint4 qh[2], ql[2];
    #pragma unroll
    for (int f = 0; f < 2; f++) {
        const size_t qidx = ((size_t)head * (Ndim / 16) + (qb >> 4) + f) * 32 + lane;
        qh[f] = g_Qh[qidx];
        ql[f] = g_Ql[qidx];
    }

    const uint32_t ones = (g == 0) ? 0x3C003C00u : 0u;

    float o[2][8];
    float lac[2][4];
    #pragma unroll
    for (int f = 0; f < 2; f++) {
        #pragma unroll
        for (int i = 0; i < 8; i++) o[f][i] = 0.f;
        #pragma unroll
        for (int i = 0; i < 4; i++) lac[f][i] = 0.f;
    }

    const int kb0 = sp * (MCHUNK / 16);
    const int nkb = MCHUNK / 16;                       // 32

    // per-thread cp.async source: warp 0 -> Kh, 1 -> Kl, 2 -> Vh
    const size_t hb = (size_t)head * (Mdim / 16) * 32;
    const uint4* gsrc =
        (warp == 0) ? (g_Kh + hb + lane) :
        (warp == 1) ? (g_Kl + hb + lane) :
                      (g_Vh + hb + lane);
    const bool producer = (tid < 96);

    // prologue: stages 0 and 1
    if (producer)
        cp_async16((uint32_t)__cvta_generic_to_shared(&sbuf[0][warp * 32 + lane]),
                   gsrc + (size_t)kb0 * 32);
    CP_COMMIT();
    if (producer)
        cp_async16((uint32_t)__cvta_generic_to_shared(&sbuf[1][warp * 32 + lane]),
                   gsrc + (size_t)(kb0 + 1) * 32);
    CP_COMMIT();

    #pragma unroll 4
    for (int i = 0; i < nkb; i++) {
        CP_WAIT1();
        __syncthreads();

        const int st = i % 3;
        const uint4 kh = sbuf[st][lane];
        const uint4 kl = sbuf[st][32 + lane];
        const uint4 vv = sbuf[st][64 + lane];

        #pragma unroll
        for (int f = 0; f < 2; f++) {
            float s0, s1, s2, s3;
            mma_f16_c(s0, s1, s2, s3, qh[f].x, qh[f].y, qh[f].z, qh[f].w, kh.x, kh.y, -SHIFT);
            mma_f16  (s0, s1, s2, s3, ql[f].x, ql[f].y, ql[f].z, ql[f].w, kh.x, kh.y);
            mma_f16  (s0, s1, s2, s3, qh[f].x, qh[f].y, qh[f].z, qh[f].w, kl.x, kl.y);
            float u0, u1, u2, u3;
            mma_f16_c(u0, u1, u2, u3, qh[f].x, qh[f].y, qh[f].z, qh[f].w, kh.z, kh.w, -SHIFT);
            mma_f16  (u0, u1, u2, u3, ql[f].x, ql[f].y, ql[f].z, ql[f].w, kh.z, kh.w);
            mma_f16  (u0, u1, u2, u3, qh[f].x, qh[f].y, qh[f].z, qh[f].w, kl.z, kl.w);

            const uint32_t a0 = pack_h2(ex2f(s0), ex2f(s1));
            const uint32_t a1 = pack_h2(ex2f(s2), ex2f(s3));
            const uint32_t a2 = pack_h2(ex2f(u0), ex2f(u1));
            const uint32_t a3 = pack_h2(ex2f(u2), ex2f(u3));

            mma_f16(lac[f][0], lac[f][1], lac[f][2], lac[f][3], a0, a1, a2, a3, ones, ones);
            mma_f16(o[f][0], o[f][1], o[f][2], o[f][3], a0, a1, a2, a3, vv.x, vv.y);
            mma_f16(o[f][4], o[f][5], o[f][6], o[f][7], a0, a1, a2, a3, vv.z, vv.w);
        }

        // issue stage i+2 (overwrites buffer last read at iteration i-1;
        // the barrier above guarantees all warps are past it)
        if (i + 2 < nkb && producer)
            cp_async16((uint32_t)__cvta_generic_to_shared(&sbuf[(i + 2) % 3][warp * 32 + lane]),
                       gsrc + (size_t)(kb0 + i + 2) * 32);
        CP_COMMIT();
    }

    const size_t pb = ((size_t)head * SPLIT + sp) * Ndim;
    #pragma unroll
    for (int f = 0; f < 2; f++) {
        const int rlo = qb + 16*f + g;
        const int rhi = rlo + 8;
        if (t == 0) {
            g_Pl[pb + rlo] = lac[f][0];
            g_Pl[pb + rhi] = lac[f][2];
        }
        #pragma unroll
        for (int c = 0; c < 2; c++) {
            const int d0 = 8 * c + 2 * t;
            *reinterpret_cast<float2*>(g_Po + (pb + rlo) * Ddim + d0) =
                make_float2(o[f][4*c+0], o[f][4*c+1]);
            *reinterpret_cast<float2*>(g_Po + (pb + rhi) * Ddim + d0) =
                make_float2(o[f][4*c+2], o[f][4*c+3]);
        }
    }
}

// ---------------------------------------------------------------------------
// Kernel 2b: combine — one thread per (head, n, d-quad), fully coalesced.
// ---------------------------------------------------------------------------
__global__ __launch_bounds__(128) void combine_kernel(const float* __restrict__ bt)
{
    const int idx  = blockIdx.x * 128 + threadIdx.x;
    const int head = idx >> 13;
    const int n    = (idx >> 2) & (Ndim - 1);
    const int quad = idx & 3;

    float L = 0.f;
    float4 o = make_float4(0.f, 0.f, 0.f, 0.f);
    #pragma unroll
    for (int s = 0; s < SPLIT; s++) {
        const size_t pb = ((size_t)head * SPLIT + s) * Ndim + n;
        L += g_Pl[pb];
        const float4 v = reinterpret_cast<const float4*>(g_Po)[pb * 4 + quad];
        o.x += v.x; o.y += v.y; o.z += v.z; o.w += v.w;
    }
    const float inv = 1.f / L;

    const int b = head >> 3, k = head & 7;
    const float4 bb = reinterpret_cast<const float4*>(bt)[k * 4 + quad];
    float4 r;
    r.x = o.x * inv + bb.x;
    r.y = o.y * inv + bb.y;
    r.z = o.z * inv + bb.z;
    r.w = o.w * inv + bb.w;
    reinterpret_cast<float4*>(g_O)[(((size_t)(b * Ndim + n)) * Kdim + k) * 4 + quad] = r;
}

// ---------------------------------------------------------------------------
// Kernel 3: output projection as fp16 hi/lo tensor-core GEMM.
// ---------------------------------------------------------------------------
__global__ __launch_bounds__(128) void out_kernel(float* __restrict__ out)
{
    const int row0 = blockIdx.x * 16;
    const int warp = threadIdx.x >> 5;
    const int lane = threadIdx.x & 31;
    const int g = lane >> 2, t = lane & 3;

    float acc[4][4];
    #pragma unroll
    for (int e4 = 0; e4 < 4; e4++)
        #pragma unroll
        for (int i = 0; i < 4; i++) acc[e4][i] = 0.f;

    const float* Orl = g_O + (size_t)(row0 + g    ) * 128;
    const float* Orh = g_O + (size_t)(row0 + g + 8) * 128;

    #pragma unroll
    for (int kc = 0; kc < 8; kc++) {
        const float2 xA = *reinterpret_cast<const float2*>(Orl + kc * 16 + 2 * t);
        const float2 yA = *reinterpret_cast<const float2*>(Orh + kc * 16 + 2 * t);
        const float2 xB = *reinterpret_cast<const float2*>(Orl + kc * 16 + 2 * t + 8);
        const float2 yB = *reinterpret_cast<const float2*>(Orh + kc * 16 + 2 * t + 8);
        const uint32_t ah0 = pack_h2(xA.x, xA.y), al0 = split_lo(xA.x, xA.y, ah0);
        const uint32_t ah1 = pack_h2(yA.x, yA.y), al1 = split_lo(yA.x, yA.y, ah1);
        const uint32_t ah2 = pack_h2(xB.x, xB.y), al2 = split_lo(xB.x, xB.y, ah2);
        const uint32_t ah3 = pack_h2(yB.x, yB.y), al3 = split_lo(yB.x, yB.y, ah3);

        #pragma unroll
        for (int e4 = 0; e4 < 4; e4++) {
            const uint4 wv = g_W[(kc * 16 + (warp * 4 + e4)) * 32 + lane];
            mma_f16(acc[e4][0], acc[e4][1], acc[e4][2], acc[e4][3], ah0, ah1, ah2, ah3, wv.x, wv.y);
            mma_f16(acc[e4][0], acc[e4][1], acc[e4][2], acc[e4][3], al0, al1, al2, al3, wv.x, wv.y);
            mma_f16(acc[e4][0], acc[e4][1], acc[e4][2], acc[e4][3], ah0, ah1, ah2, ah3, wv.z, wv.w);
        }
    }

    #pragma unroll
    for (int e4 = 0; e4 < 4; e4++) {
        const int e0 = (warp * 4 + e4) * 8 + 2 * t;
        *reinterpret_cast<float2*>(out + (size_t)(row0 + g    ) * Edim + e0) =
            make_float2(acc[e4][0], acc[e4][1]);
        *reinterpret_cast<float2*>(out + (size_t)(row0 + g + 8) * Edim + e0) =
            make_float2(acc[e4][2], acc[e4][3]);
    }
}

extern "C" void kernel_launch(void* const* d_in, const int* in_sizes, int n_in,
                              void* d_out, int out_size)
{
    const float* x  = (const float*)d_in[0];
    const float* y  = (const float*)d_in[1];
    const float* l1 = (const float*)d_in[2];
    const float* l2 = (const float*)d_in[3];
    const float* t1 = (const float*)d_in[4];
    const float* t2 = (const float*)d_in[5];
    const float* bl = (const float*)d_in[6];
    const float* bt = (const float*)d_in[7];

    prep_w<<<32, 128>>>(t2);
    prep_proj_w<<<96, 128>>>(l1, t1, l2);
    proj_mma<<<dim3(64, 4, 2), 128>>>(x, y, bl);
    flash_kernel<<<dim3(Ndim / 128, NHEAD, SPLIT), 128>>>();
    combine_kernel<<<NHEAD * Ndim * 4 / 128, 128>>>(bt);
    out_kernel<<<Bdim * Ndim / 16, 128>>>((float*)d_out);
}